// round 12
// baseline (speedup 1.0000x reference)
#include <cuda_runtime.h>
#include <cuda_bf16.h>
#include <math.h>

#define DD 256
#define NB 3072
#define NCHUNK 8
#define KVSLOT 66560   /* 4*4*64*64 + 4*4*64 */

#define OFF_PROJ  0
#define SZ_PROJ   (8*3*DD*DD)
#define OFF_MERGE (OFF_PROJ + SZ_PROJ)
#define SZ_MERGE  (8*DD*DD)
#define OFF_MLP1  (OFF_MERGE + SZ_MERGE)
#define SZ_MLP1   (8*2*DD*2*DD)
#define OFF_MLP2  (OFF_MLP1 + SZ_MLP1)
#define SZ_MLP2   (8*DD*2*DD)
#define OFF_GAT   (OFF_MLP2 + SZ_MLP2)
#define SZ_GAT    (4*DD*DD)
#define OFF_FIN   (OFF_GAT + SZ_GAT)
#define SZ_FIN    (DD*DD)
#define WTOT      (OFF_FIN + SZ_FIN)

__device__ float g_act[6*DD*NB];
__device__ float g_qkv[(size_t)4*3*DD*NB];
__device__ float g_ob[4*DD*NB];
__device__ float g_msg[4*DD*NB];
__device__ float g_tb[(size_t)4*2*DD*NB];
__device__ float g_agg[2*DD*NB];
__device__ float g_fb[4*DD*NB];
__device__ unsigned short g_fbh[4*DD*NB], g_fbl[4*DD*NB];
__device__ float g_sc[(size_t)2*NB*NB];
__device__ float g_kvpart[NCHUNK*KVSLOT];
__device__ float g_kvred[KVSLOT];
__device__ float g_wa[4*2*DD];
__device__ float g_rmax[2*NB];
__device__ float g_rsum[2*NB];
__device__ float g_cmax[2*NB];
__device__ float g_csum[2*NB];
__device__ int   g_i0[NB];
__device__ int   g_i1[NB];
__device__ int   g_valid0[NB];
__device__ float g_m0[NB];
__device__ float g_m1[NB];
__device__ float g_ms0buf[NB];
__device__ unsigned short g_wbh[WTOT], g_wbl[WTOT];

__device__ __forceinline__ unsigned packbf(float lo, float hi){
    unsigned r; asm("cvt.rn.bf16x2.f32 %0,%1,%2;":"=r"(r):"f"(hi),"f"(lo)); return r;
}
__device__ __forceinline__ unsigned short bf1(float v){
    __nv_bfloat16 b = __float2bfloat16(v);
    return *reinterpret_cast<unsigned short*>(&b);
}
__device__ __forceinline__ float bf2f(unsigned short u){
    return __uint_as_float(((unsigned)u) << 16);
}
__device__ __forceinline__ unsigned prmt(unsigned a, unsigned b, unsigned s){
    unsigned r; asm("prmt.b32 %0,%1,%2,%3;":"=r"(r):"r"(a),"r"(b),"r"(s)); return r;
}
__device__ __forceinline__ void mma16(float* c, const unsigned* a, const unsigned* b){
    asm volatile("mma.sync.aligned.m16n8k16.row.col.f32.bf16.bf16.f32 "
        "{%0,%1,%2,%3}, {%4,%5,%6,%7}, {%8,%9}, {%0,%1,%2,%3};"
        : "+f"(c[0]),"+f"(c[1]),"+f"(c[2]),"+f"(c[3])
        : "r"(a[0]),"r"(a[1]),"r"(a[2]),"r"(a[3]), "r"(b[0]),"r"(b[1]));
}

__global__ void cvt_all(const float* __restrict__ projw, const float* __restrict__ mergew,
                        const float* __restrict__ mlp1w, const float* __restrict__ mlp2w,
                        const float* __restrict__ gatW,  const float* __restrict__ finw,
                        unsigned short* __restrict__ H, unsigned short* __restrict__ L)
{
    int i = blockIdx.x*256 + threadIdx.x;
    if (i >= WTOT/4) return;
    int e = i*4;
    const float* src;
    if      (e < OFF_MERGE) src = projw  + (e - OFF_PROJ);
    else if (e < OFF_MLP1)  src = mergew + (e - OFF_MERGE);
    else if (e < OFF_MLP2)  src = mlp1w  + (e - OFF_MLP1);
    else if (e < OFF_GAT)   src = mlp2w  + (e - OFF_MLP2);
    else if (e < OFF_FIN)   src = gatW   + (e - OFF_GAT);
    else                    src = finw   + (e - OFF_FIN);
    float4 v = *(const float4*)src;
    unsigned h01 = packbf(v.x, v.y), h23 = packbf(v.z, v.w);
    ((uint2*)H)[i] = make_uint2(h01, h23);
    float lx = v.x - __uint_as_float(h01<<16);
    float ly = v.y - __uint_as_float(h01&0xffff0000u);
    float lz = v.z - __uint_as_float(h23<<16);
    float lw = v.w - __uint_as_float(h23&0xffff0000u);
    ((uint2*)L)[i] = make_uint2(packbf(lx,ly), packbf(lz,lw));
}

/* BF16x3 GEMM, templated CTA tile height BM (64 or 128), BN=64, BK=32,
   128 threads (4 warps 2x2), warp tile (BM/2)x32. Double-buffered smem,
   packed B stores, conflict-free strides (A: 20, B: 72). */
template<int BM>
__global__ void __launch_bounds__(128) gemm_tc(
    const unsigned short* __restrict__ Wh, const unsigned short* __restrict__ Wl,
    long long wz, int wtrans, int O,
    const float* __restrict__ Xa, long long xaz,
    const float* __restrict__ Xb, long long xbz, int csplit,
    const float* __restrict__ bias,
    const float* __restrict__ res, long long resz,
    float* __restrict__ Out, long long outz,
    int C, int N, float alpha, int act)
{
    constexpr int MT = BM/32;     /* mma tiles per warp in M */
    constexpr int AI = BM/8;      /* per-thread A words (!wtrans) */
    constexpr int AW = BM/16;     /* per-thread A pair-loads (wtrans) */
    __shared__ unsigned sAh[2][BM][20], sAl[2][BM][20];
    __shared__ unsigned sBh[2][16][72], sBl[2][16][72];
    const int z  = blockIdx.z;
    const int o0 = blockIdx.y * BM, j0 = blockIdx.x * 64;
    const unsigned* WhU = (const unsigned*)(Wh + (size_t)z*(size_t)wz);
    const unsigned* WlU = (const unsigned*)(Wl + (size_t)z*(size_t)wz);
    const float* Xaz = Xa + (size_t)z*(size_t)xaz;
    const float* Xbz = Xb + (size_t)z*(size_t)xbz;
    const int tid  = threadIdx.x;
    const int lane = tid & 31, w = tid >> 5;
    const int wm = w >> 1, wn = w & 1;
    const int g = lane >> 2, t = lane & 3;
    const int C2 = C >> 1, O2 = O >> 1;
    const int bn = tid & 63, cb = (tid >> 6) * 16;

    float acc[MT][4][4];
    #pragma unroll
    for (int i=0;i<MT;i++)
        #pragma unroll
        for (int j=0;j<4;j++)
            #pragma unroll
            for (int k=0;k<4;k++) acc[i][j][k]=0.f;

    unsigned ah0[AI], al0[AI], ah1[AW], al1[AW];
    float bpre[16];

#define B_FLUSH(bu) do {                                                      \
    _Pragma("unroll")                                                         \
    for (int jj2 = 0; jj2 < 8; jj2++) {                                       \
        float v0 = bpre[2*jj2], v1 = bpre[2*jj2+1];                           \
        unsigned hw = packbf(v0, v1);                                         \
        float h0 = __uint_as_float(hw << 16);                                 \
        float h1 = __uint_as_float(hw & 0xffff0000u);                         \
        unsigned lw = packbf(v0 - h0, v1 - h1);                               \
        int p = (cb >> 1) + jj2;                                              \
        sBh[bu][p][bn] = hw;                                                  \
        sBl[bu][p][bn] = lw;                                                  \
    }                                                                         \
} while(0)

    if (!wtrans) {
        #pragma unroll
        for (int i = 0; i < AI; i++) {
            int idx = tid + i*128;
            int o = idx >> 4, p = idx & 15;
            size_t a = (size_t)(o0+o)*C2 + p;
            ah0[i] = WhU[a]; al0[i] = WlU[a];
        }
    } else {
        #pragma unroll
        for (int i = 0; i < AW; i++) {
            int idx = tid + i*128;
            int p = idx & 15, op = idx >> 4;
            size_t r0 = (size_t)(2*p)*O2 + ((o0 + 2*op) >> 1);
            ah0[i] = WhU[r0]; ah1[i] = WhU[r0 + O2];
            al0[i] = WlU[r0]; al1[i] = WlU[r0 + O2];
        }
    }
    #pragma unroll
    for (int i = 0; i < 16; i++) {
        int c = cb + i;
        const float* xp = (c < csplit) ? Xaz + (size_t)c*N
                                       : Xbz + (size_t)(c-csplit)*N;
        bpre[i] = xp[j0 + bn];
    }
    if (!wtrans) {
        #pragma unroll
        for (int i = 0; i < AI; i++) {
            int idx = tid + i*128;
            int o = idx >> 4, p = idx & 15;
            sAh[0][o][p] = ah0[i]; sAl[0][o][p] = al0[i];
        }
    } else {
        #pragma unroll
        for (int i = 0; i < AW; i++) {
            int idx = tid + i*128;
            int p = idx & 15, op = idx >> 4, o = 2*op;
            sAh[0][o][p]   = prmt(ah0[i], ah1[i], 0x5410);
            sAh[0][o+1][p] = prmt(ah0[i], ah1[i], 0x7632);
            sAl[0][o][p]   = prmt(al0[i], al1[i], 0x5410);
            sAl[0][o+1][p] = prmt(al0[i], al1[i], 0x7632);
        }
    }
    B_FLUSH(0);
    __syncthreads();

    const int ntiles = C >> 5;
    for (int kt = 0; kt < ntiles; kt++) {
        const int cur = kt & 1, nxt = cur ^ 1;
        const bool more = (kt + 1 < ntiles);
        if (more) {
            int k0 = (kt + 1) << 5;
            if (!wtrans) {
                #pragma unroll
                for (int i = 0; i < AI; i++) {
                    int idx = tid + i*128;
                    int o = idx >> 4, p = idx & 15;
                    size_t a = (size_t)(o0+o)*C2 + (k0>>1) + p;
                    ah0[i] = WhU[a]; al0[i] = WlU[a];
                }
            } else {
                #pragma unroll
                for (int i = 0; i < AW; i++) {
                    int idx = tid + i*128;
                    int p = idx & 15, op = idx >> 4;
                    size_t r0 = (size_t)(k0 + 2*p)*O2 + ((o0 + 2*op) >> 1);
                    ah0[i] = WhU[r0]; ah1[i] = WhU[r0 + O2];
                    al0[i] = WlU[r0]; al1[i] = WlU[r0 + O2];
                }
            }
            #pragma unroll
            for (int i = 0; i < 16; i++) {
                int cg = k0 + cb + i;
                const float* xp = (cg < csplit) ? Xaz + (size_t)cg*N
                                                : Xbz + (size_t)(cg-csplit)*N;
                bpre[i] = xp[j0 + bn];
            }
        }
        #pragma unroll
        for (int s = 0; s < 2; s++) {
            int s8 = s*8;
            unsigned ah[MT][4], al[MT][4], bh[4][2], bl[4][2];
            #pragma unroll
            for (int mt = 0; mt < MT; mt++) {
                int r0 = wm*(BM/2) + mt*16 + g;
                ah[mt][0]=sAh[cur][r0][s8+t];    al[mt][0]=sAl[cur][r0][s8+t];
                ah[mt][1]=sAh[cur][r0+8][s8+t];  al[mt][1]=sAl[cur][r0+8][s8+t];
                ah[mt][2]=sAh[cur][r0][s8+t+4];  al[mt][2]=sAl[cur][r0][s8+t+4];
                ah[mt][3]=sAh[cur][r0+8][s8+t+4];al[mt][3]=sAl[cur][r0+8][s8+t+4];
            }
            #pragma unroll
            for (int nt = 0; nt < 4; nt++) {
                int cc = wn*32 + nt*8 + g;
                bh[nt][0]=sBh[cur][s8+t][cc];   bl[nt][0]=sBl[cur][s8+t][cc];
                bh[nt][1]=sBh[cur][s8+t+4][cc]; bl[nt][1]=sBl[cur][s8+t+4][cc];
            }
            #pragma unroll
            for (int mt = 0; mt < MT; mt++)
                #pragma unroll
                for (int nt = 0; nt < 4; nt++) {
                    mma16(acc[mt][nt], ah[mt], bh[nt]);
                    mma16(acc[mt][nt], ah[mt], bl[nt]);
                    mma16(acc[mt][nt], al[mt], bh[nt]);
                }
        }
        if (more) {
            if (!wtrans) {
                #pragma unroll
                for (int i = 0; i < AI; i++) {
                    int idx = tid + i*128;
                    int o = idx >> 4, p = idx & 15;
                    sAh[nxt][o][p] = ah0[i]; sAl[nxt][o][p] = al0[i];
                }
            } else {
                #pragma unroll
                for (int i = 0; i < AW; i++) {
                    int idx = tid + i*128;
                    int p = idx & 15, op = idx >> 4, o = 2*op;
                    sAh[nxt][o][p]   = prmt(ah0[i], ah1[i], 0x5410);
                    sAh[nxt][o+1][p] = prmt(ah0[i], ah1[i], 0x7632);
                    sAl[nxt][o][p]   = prmt(al0[i], al1[i], 0x5410);
                    sAl[nxt][o+1][p] = prmt(al0[i], al1[i], 0x7632);
                }
            }
            B_FLUSH(nxt);
        }
        __syncthreads();
    }
    #pragma unroll
    for (int mt = 0; mt < MT; mt++) {
        #pragma unroll
        for (int nt = 0; nt < 4; nt++) {
            int row0 = o0 + wm*(BM/2) + mt*16 + g;
            int col0 = j0 + wn*32 + nt*8 + 2*t;
            #pragma unroll
            for (int e = 0; e < 4; e++) {
                int o  = row0 + (e >> 1)*8;
                int jj = col0 + (e & 1);
                float v = acc[mt][nt][e]*alpha + (bias ? bias[o] : 0.f);
                if (act == 2) v = v > 0.f ? v : (__expf(v) - 1.f);
                size_t off = (size_t)z*(size_t)outz + (size_t)o*N + jj;
                if (res) v += res[(size_t)z*(size_t)resz + (size_t)o*N + jj];
                Out[off] = v;
            }
        }
    }
#undef B_FLUSH
}

/* linear attention stage 1: z in 0..3 pseudo-batch (stream x batch) */
__global__ void __launch_bounds__(256) attn_kv_kernel(
    const float* __restrict__ K, long long kz,
    const float* __restrict__ V, long long vz,
    float* __restrict__ part, int ns)
{
    int chunk = blockIdx.x, h = blockIdx.y, z = blockIdx.z;
    int mlen = ns / NCHUNK, m0 = chunk * mlen;
    const float* Kb = K + (size_t)z*(size_t)kz;
    const float* Vb = V + (size_t)z*(size_t)vz;
    __shared__ float ks[64][36];
    __shared__ float vs[64][36];
    int tid = threadIdx.x;
    int qi0 = (tid>>4)*4, ki0 = (tid&15)*4;
    float acc[4][4]={{0,0,0,0},{0,0,0,0},{0,0,0,0},{0,0,0,0}};
    float ksum = 0.f, invm = 1.f/(float)ns;
    for (int mt = 0; mt < mlen; mt += 32) {
        __syncthreads();
        for (int idx = tid; idx < 64*32; idx += 256) {
            int d = idx>>5, mm = idx&31, m = m0+mt+mm;
            float kr = Kb[(size_t)(d*4+h)*ns + m];
            ks[d][mm] = kr>0.f ? kr+1.f : __expf(kr);
            vs[d][mm] = Vb[(size_t)(d*4+h)*ns + m]*invm;
        }
        __syncthreads();
        if (tid < 64) {
            #pragma unroll
            for (int mm=0;mm<32;mm++) ksum += ks[tid][mm];
        }
        #pragma unroll
        for (int mm4=0; mm4<8; mm4++){
            float4 vv[4], kv[4];
            #pragma unroll
            for (int i=0;i<4;i++) vv[i] = *(const float4*)&vs[qi0+i][mm4*4];
            #pragma unroll
            for (int j=0;j<4;j++) kv[j] = *(const float4*)&ks[ki0+j][mm4*4];
            #pragma unroll
            for (int i=0;i<4;i++)
                #pragma unroll
                for (int j=0;j<4;j++)
                    acc[i][j] += vv[i].x*kv[j].x + vv[i].y*kv[j].y
                               + vv[i].z*kv[j].z + vv[i].w*kv[j].w;
        }
    }
    float* dst = part + (size_t)chunk*KVSLOT;
    size_t base = (size_t)(z*4+h)*64;
    #pragma unroll
    for (int i=0;i<4;i++)
        #pragma unroll
        for (int j=0;j<4;j++)
            dst[(base+qi0+i)*64 + ki0+j] = acc[i][j];
    if (tid < 64) dst[65536 + base + tid] = ksum;
}

__global__ void kv_reduce_kernel(const float* __restrict__ part, float* __restrict__ o)
{
    int i = blockIdx.x*256 + threadIdx.x;
    if (i < KVSLOT) {
        float s = 0.f;
        #pragma unroll
        for (int c=0;c<NCHUNK;c++) s += part[(size_t)c*KVSLOT + i];
        o[i] = s;
    }
}

__global__ void __launch_bounds__(128) attn_out_kernel(
    const float* __restrict__ Q, long long qz, const float* __restrict__ KVr,
    float* __restrict__ O_, long long oz, int nq, int ns)
{
    int z = blockIdx.z, h = blockIdx.y;
    int m = blockIdx.x*128 + threadIdx.x;
    __shared__ float kvs[64][64];
    __shared__ float kss[64];
    const float* src = KVr + (size_t)(z*4+h)*4096;
    for (int i = threadIdx.x; i < 4096; i += 128) kvs[i>>6][i&63] = src[i];
    if (threadIdx.x < 64) kss[threadIdx.x] = KVr[65536 + (size_t)(z*4+h)*64 + threadIdx.x];
    __syncthreads();
    const float* Qb = Q + (size_t)z*(size_t)qz;
    float qv[64], denom = 0.f;
    #pragma unroll
    for (int d=0;d<64;d++){
        float q = Qb[(size_t)(d*4+h)*nq + m];
        q = q>0.f ? q+1.f : __expf(q);
        qv[d]=q; denom += q*kss[d];
    }
    float zf = (float)ns/(denom + 1e-6f);
    float* Ob = O_ + (size_t)z*(size_t)oz;
    for (int qd=0; qd<64; qd++){
        const float4* kv4 = (const float4*)kvs[qd];
        float accv = 0.f;
        #pragma unroll
        for (int d4=0; d4<16; d4++){
            float4 kk = kv4[d4];
            accv += qv[d4*4]*kk.x + qv[d4*4+1]*kk.y
                  + qv[d4*4+2]*kk.z + qv[d4*4+3]*kk.w;
        }
        Ob[(size_t)(qd*4+h)*nq + m] = accv*zf;
    }
}

__global__ void __launch_bounds__(256) instnorm_relu_kernel(float* X, int C, int n)
{
    int c = blockIdx.x, b = blockIdx.y;
    float* row = X + ((size_t)b*C + c)*n;
    int tid = threadIdx.x;
    float s=0.f, s2=0.f;
    for (int i=tid;i<n;i+=256){ float v=row[i]; s+=v; s2+=v*v; }
    __shared__ float sm1[256], sm2[256];
    sm1[tid]=s; sm2[tid]=s2; __syncthreads();
    for (int st=128;st;st>>=1){
        if (tid<st){ sm1[tid]+=sm1[tid+st]; sm2[tid]+=sm2[tid+st]; }
        __syncthreads();
    }
    float mean = sm1[0]/(float)n;
    float var = sm2[0]/(float)n - mean*mean;
    float rstd = rsqrtf(var + 1e-5f);
    for (int i=tid;i<n;i+=256){
        float v = (row[i]-mean)*rstd;
        row[i] = v>0.f ? v : 0.f;
    }
}

__global__ void gat_vec_kernel(const float* __restrict__ gatW,
                               const float* __restrict__ gata, float* __restrict__ wa)
{
    int gg = blockIdx.x, d = threadIdx.x;
    const float* W = gatW + (size_t)gg*DD*DD;
    const float* a = gata + (size_t)gg*2*DD;
    float s1=0.f, s2=0.f;
    for (int o=0;o<DD;o++){ float w=W[(size_t)d*DD+o]; s1+=w*a[o]; s2+=w*a[DD+o]; }
    wa[gg*2*DD + d] = s1;
    wa[gg*2*DD + DD + d] = s2;
}

__global__ void __launch_bounds__(256) gat_agg_kernel(
    const float* __restrict__ d3, const float* __restrict__ d2d,
    const float* __restrict__ wa, float* __restrict__ agg, int n)
{
    int b = blockIdx.y;
    int warp = threadIdx.x>>5, lane = threadIdx.x&31;
    int nn = blockIdx.x*8 + warp;
    const float* Wa1 = wa;
    const float* Wa2 = wa + DD;
    const float* d3b = d3 + (size_t)b*DD*n;
    const float* d2b = d2d + (size_t)b*DD*(size_t)n*8;
    size_t n8 = (size_t)n*8;
    float x3[8], w2v[8];
    float sself=0.f, s0=0.f;
    #pragma unroll
    for (int r=0;r<8;r++){
        int d = lane + r*32;
        x3[r]=d3b[(size_t)d*n+nn]; w2v[r]=Wa2[d];
        sself += x3[r]*Wa1[d]; s0 += x3[r]*w2v[r];
    }
    #pragma unroll
    for (int off=16;off;off>>=1){
        sself += __shfl_xor_sync(0xffffffffu, sself, off);
        s0    += __shfl_xor_sync(0xffffffffu, s0, off);
    }
    float e[9]; e[0] = sself + s0;
    size_t nbase = (size_t)nn*8;
    #pragma unroll
    for (int l=1;l<9;l++){
        float sl = 0.f;
        #pragma unroll
        for (int r=0;r<8;r++)
            sl += d2b[(size_t)(lane+r*32)*n8 + nbase + (l-1)] * w2v[r];
        #pragma unroll
        for (int off=16;off;off>>=1) sl += __shfl_xor_sync(0xffffffffu, sl, off);
        e[l] = sself + sl;
    }
    float mx = -1e30f;
    #pragma unroll
    for (int l=0;l<9;l++){ e[l] = e[l]>0.f ? e[l] : 0.2f*e[l]; mx = fmaxf(mx, e[l]); }
    float sum = 0.f;
    #pragma unroll
    for (int l=0;l<9;l++){ e[l] = __expf(e[l]-mx); sum += e[l]; }
    float inv = 1.f/sum;
    float accv[8];
    #pragma unroll
    for (int r=0;r<8;r++) accv[r] = e[0]*inv*x3[r];
    #pragma unroll
    for (int l=1;l<9;l++){
        float al = e[l]*inv;
        #pragma unroll
        for (int r=0;r<8;r++)
            accv[r] += al * d2b[(size_t)(lane+r*32)*n8 + nbase + (l-1)];
    }
    float* ab = agg + (size_t)b*DD*n;
    #pragma unroll
    for (int r=0;r<8;r++) ab[(size_t)(lane+r*32)*n + nn] = accv[r];
}

__global__ void colnorm_kernel(float* X, unsigned short* H, unsigned short* L, int n)
{
    int b = blockIdx.y;
    int col = blockIdx.x*256 + threadIdx.x;
    size_t zb = (size_t)b*DD*n;
    float* Xb = X + zb;
    float s = 0.f;
    for (int d=0;d<DD;d++){ float v=Xb[(size_t)d*n+col]; s += v*v; }
    float inv = 1.f / fmaxf(sqrtf(s), 1e-12f);
    for (int d=0;d<DD;d++){
        float v = Xb[(size_t)d*n+col]*inv;
        Xb[(size_t)d*n+col] = v;
        unsigned short hb = bf1(v);
        H[zb + (size_t)d*n + col] = hb;
        L[zb + (size_t)d*n + col] = bf1(v - bf2f(hb));
    }
}

__global__ void __launch_bounds__(256) row_stats_kernel(
    const float* __restrict__ S, float* rmax, float* rsum, int n1, int n2)
{
    int br = blockIdx.y*n1 + blockIdx.x;
    const float* row = S + (size_t)br*n2;
    int tid = threadIdx.x;
    __shared__ float sm[256];
    float mx = -1e30f;
    for (int j=tid;j<n2;j+=256) mx = fmaxf(mx, row[j]);
    sm[tid]=mx; __syncthreads();
    for (int st=128;st;st>>=1){ if (tid<st) sm[tid]=fmaxf(sm[tid],sm[tid+st]); __syncthreads(); }
    mx = sm[0]; __syncthreads();
    float s = 0.f;
    for (int j=tid;j<n2;j+=256) s += __expf(row[j]-mx);
    sm[tid]=s; __syncthreads();
    for (int st=128;st;st>>=1){ if (tid<st) sm[tid]+=sm[tid+st]; __syncthreads(); }
    if (tid==0){ rmax[br]=mx; rsum[br]=sm[0]; }
}

__global__ void col_stats_kernel(const float* __restrict__ S,
                                 float* cmax, float* csum, int n1, int n2)
{
    int b = blockIdx.y;
    int c = blockIdx.x*256 + threadIdx.x;
    const float* Sb = S + (size_t)b*n1*n2;
    float mx = -1e30f, s = 0.f;
    for (int r=0;r<n1;r++){
        float v = Sb[(size_t)r*n2 + c];
        if (v > mx){ s = s*__expf(mx-v) + 1.f; mx = v; }
        else s += __expf(v-mx);
    }
    cmax[b*n1 + c] = mx;
    csum[b*n1 + c] = s;
}

__global__ void conf_kernel(const float* __restrict__ S,
    const float* __restrict__ rmax, const float* __restrict__ rsum,
    const float* __restrict__ cmax, const float* __restrict__ csum,
    float* __restrict__ conf)
{
    size_t idx = (size_t)blockIdx.x*256 + threadIdx.x;
    int z = (int)(idx / ((size_t)NB*NB));
    size_t rem = idx - (size_t)z*NB*NB;
    int n = (int)(rem / NB), m = (int)(rem % NB);
    float s = S[idx];
    conf[idx] = __expf(2.f*s - rmax[z*NB+n] - cmax[z*NB+m])
                / (rsum[z*NB+n]*csum[z*NB+m]);
}

__global__ void __launch_bounds__(256) rowargmax_kernel(
    const float* __restrict__ conf0, int* i0, float* m0)
{
    int n = blockIdx.x;
    const float* row = conf0 + (size_t)n*NB;
    int tid = threadIdx.x;
    float best = -1e30f; int bidx = 0;
    for (int m=tid;m<NB;m+=256){ float v=row[m]; if (v>best){best=v;bidx=m;} }
    __shared__ float bv[256]; __shared__ int bi[256];
    bv[tid]=best; bi[tid]=bidx; __syncthreads();
    for (int st=128;st;st>>=1){
        if (tid<st){
            if (bv[tid+st]>bv[tid] || (bv[tid+st]==bv[tid] && bi[tid+st]<bi[tid])){
                bv[tid]=bv[tid+st]; bi[tid]=bi[tid+st];
            }
        }
        __syncthreads();
    }
    if (tid==0){ i0[n]=bi[0]; m0[n]=bv[0]; }
}

__global__ void colargmax_kernel(const float* __restrict__ conf0, int* i1, float* m1)
{
    int m = blockIdx.x*256 + threadIdx.x;
    float best = -1e30f; int bidx = 0;
    for (int n=0;n<NB;n++){
        float v = conf0[(size_t)n*NB + m];
        if (v > best){ best=v; bidx=n; }
    }
    i1[m]=bidx; m1[m]=best;
}

__global__ void match0_kernel(const int* i0, const int* i1, const float* m0,
                              float* out, float* ms0buf, int* valid0)
{
    int n = blockIdx.x*256 + threadIdx.x;
    int t = i0[n];
    int mutual = (i1[t] == n);
    float ms0 = mutual ? m0[n] : 0.f;
    int v0 = mutual && (ms0 > 0.2f);
    out[n] = v0 ? (float)t : -1.f;
    out[2*NB + n] = ms0;
    ms0buf[n] = ms0;
    valid0[n] = v0;
}

__global__ void match1_kernel(const int* i0, const int* i1,
                              const float* ms0buf, const int* valid0, float* out)
{
    int m = blockIdx.x*256 + threadIdx.x;
    int t = i1[m];
    int mutual = (i0[t] == m);
    float ms1 = mutual ? ms0buf[t] : 0.f;
    int v1 = mutual && valid0[t];
    out[NB + m] = v1 ? (float)t : -1.f;
    out[3*NB + m] = ms1;
}

/* --------------------------------- host ---------------------------------- */
static void* gsym(const void* s){ void* p=nullptr; cudaGetSymbolAddress(&p, s); return p; }
typedef unsigned short u16;

extern "C" void kernel_launch(void* const* d_in, const int* in_sizes, int n_in,
                              void* d_out, int out_size)
{
    const float* in_dq   = (const float*)d_in[0];
    const float* in_d3   = (const float*)d_in[1];
    const float* in_d2db = (const float*)d_in[2];
    const float* projb   = (const float*)d_in[4];
    const float* mergeb  = (const float*)d_in[6];
    const float* mlp1b   = (const float*)d_in[8];
    const float* mlp2b   = (const float*)d_in[10];
    const float* gatW    = (const float*)d_in[11];
    const float* gata    = (const float*)d_in[12];
    const float* finb    = (const float*)d_in[14];
    float* out = (float*)d_out;

    float* act    = (float*)gsym(g_act);
    float* qkv    = (float*)gsym(g_qkv);
    float* ob     = (float*)gsym(g_ob);
    float* msg    = (float*)gsym(g_msg);
    float* tb     = (float*)gsym(g_tb);
    float* agg    = (float*)gsym(g_agg);
    float* fb     = (float*)gsym(g_fb);
    u16*   fbh    = (u16*)gsym(g_fbh);
    u16*   fbl    = (u16*)gsym(g_fbl);
    float* sc     = (float*)gsym(g_sc);
    float* kvpart = (float*)gsym(g_kvpart);
    float* kvred  = (float*)gsym(g_kvred);
    float* wa     = (float*)gsym(g_wa);
    float* rmax   = (float*)gsym(g_rmax);
    float* rsum   = (float*)gsym(g_rsum);
    float* cmax   = (float*)gsym(g_cmax);
    float* csum   = (float*)gsym(g_csum);
    int*   i0     = (int*)gsym(g_i0);
    int*   i1     = (int*)gsym(g_i1);
    int*   valid0 = (int*)gsym(g_valid0);
    float* m0     = (float*)gsym(g_m0);
    float* m1     = (float*)gsym(g_m1);
    float* ms0buf = (float*)gsym(g_ms0buf);
    u16*   wbh    = (u16*)gsym(g_wbh);
    u16*   wbl    = (u16*)gsym(g_wbl);

    const int N = NB;
    const long long DN  = (long long)DD*N;
    const long long QKN = (long long)3*DD*N;
    const long long TBN = (long long)2*DD*N;
    float* dqp = act;
    float* d3p = act + 2*DN;
    float* dqo = act + 4*DN;

    cvt_all<<<(WTOT/4+255)/256,256>>>((const float*)d_in[3], (const float*)d_in[5],
                                      (const float*)d_in[7], (const float*)d_in[9],
                                      gatW, (const float*)d_in[13], wbh, wbl);

    cudaMemcpyAsync(dqp, in_dq, (size_t)2*DN*sizeof(float), cudaMemcpyDeviceToDevice);
    cudaMemcpyAsync(d3p, in_d3, (size_t)2*DN*sizeof(float), cudaMemcpyDeviceToDevice);
    gat_vec_kernel<<<4,256>>>(gatW, gata, wa);

    int gi = 0, ai = 0;
    for (int step = 0; step < 12; step++) {
        int t = step % 3;
        if (t == 0) {
            gat_agg_kernel<<<dim3(N/8,2),256>>>(d3p, in_d2db, wa + gi*2*DD, agg, N);
            gemm_tc<64><<<dim3(N/64,4,2),128>>>(wbh+OFF_GAT+(size_t)gi*DD*DD,
                wbl+OFF_GAT+(size_t)gi*DD*DD, 0,1,DD,
                agg, DN, agg, DN, DD, nullptr, nullptr,0,
                d3p, DN, DD, N, 1.f, 2);
            gi++;
        } else {
            const u16* pwh = wbh + OFF_PROJ + (size_t)ai*3*DD*DD;
            const u16* pwl = wbl + OFF_PROJ + (size_t)ai*3*DD*DD;
            const float* pb = projb + (size_t)ai*3*DD;
            if (t == 1) {
                gemm_tc<128><<<dim3(N/64,6,4),128>>>(pwh, pwl, 0,0,768,
                    act, DN, act, DN, DD, pb, nullptr,0, qkv, QKN, DD, N, 1.f, 0);
            } else {
                cudaMemcpyAsync(dqo, dqp, (size_t)2*DN*sizeof(float),
                                cudaMemcpyDeviceToDevice);
                gemm_tc<64><<<dim3(N/64,4,4),128>>>(pwh, pwl, 0,0,DD,
                    act, DN, act, DN, DD, pb, nullptr,0, qkv, QKN, DD, N, 1.f, 0);
                gemm_tc<128><<<dim3(N/64,4,4),128>>>(pwh+DD*DD, pwl+DD*DD, 0,0,512,
                    d3p, DN, d3p, DN, DD, pb+DD, nullptr,0,
                    qkv + (size_t)DD*N, QKN, DD, N, 1.f, 0);
            }
            attn_kv_kernel<<<dim3(NCHUNK,4,4),256>>>(qkv + (size_t)DD*N, QKN,
                                                     qkv + (size_t)2*DD*N, QKN,
                                                     kvpart, N);
            kv_reduce_kernel<<<(KVSLOT+255)/256,256>>>(kvpart, kvred);
            attn_out_kernel<<<dim3(N/128,4,4),128>>>(qkv, QKN, kvred, ob, DN, N, N);
            gemm_tc<64><<<dim3(N/64,4,4),128>>>(wbh+OFF_MERGE+(size_t)ai*DD*DD,
                wbl+OFF_MERGE+(size_t)ai*DD*DD, 0,0,DD,
                ob, DN, ob, DN, DD, mergeb+(size_t)ai*DD, nullptr,0,
                msg, DN, DD, N, 1.f, 0);
            gemm_tc<128><<<dim3(N/64,4,4),128>>>(wbh+OFF_MLP1+(size_t)ai*512*512,
                wbl+OFF_MLP1+(size_t)ai*512*512, 0,0,512,
                act, DN, msg, DN, DD, mlp1b+(size_t)ai*512, nullptr,0,
                tb, TBN, 512, N, 1.f, 0);
            instnorm_relu_kernel<<<dim3(512,4),256>>>(tb, 512, N);
            gemm_tc<64><<<dim3(N/64,4,4),128>>>(wbh+OFF_MLP2+(size_t)ai*DD*512,
                wbl+OFF_MLP2+(size_t)ai*DD*512, 0,0,DD,
                tb, TBN, tb, TBN, 512, mlp2b+(size_t)ai*DD, act, DN,
                act, DN, 512, N, 1.f, 0);
            ai++;
        }
    }

    gemm_tc<64><<<dim3(N/64,4,4),128>>>(wbh+OFF_FIN, wbl+OFF_FIN, 0,0,DD,
        act, DN, act, DN, DD, finb, nullptr,0, fb, DN, DD, N, 1.f, 0);
    colnorm_kernel<<<dim3(N/256,4),256>>>(fb, fbh, fbl, N);

    gemm_tc<128><<<dim3(N/64,N/128,2),128>>>(fbh, fbl, DN, 1, N,
        fb + 2*DN, DN, fb + 2*DN, DN, DD,
        nullptr, nullptr,0, sc, (long long)N*N, DD, N, 10.f, 0);
    row_stats_kernel<<<dim3(N,2),256>>>(sc, rmax, rsum, N, N);
    col_stats_kernel<<<dim3(N/256,2),256>>>(sc, cmax, csum, N, N);

    float* conf = out + 4*NB;
    conf_kernel<<<(unsigned)((size_t)2*N*N/256),256>>>(sc, rmax, rsum, cmax, csum, conf);
    rowargmax_kernel<<<N,256>>>(conf, i0, m0);
    colargmax_kernel<<<N/256,256>>>(conf, i1, m1);
    match0_kernel<<<N/256,256>>>(i0, i1, m0, out, ms0buf, valid0);
    match1_kernel<<<N/256,256>>>(i0, i1, ms0buf, valid0, out);
}

// round 13
// speedup vs baseline: 1.0644x; 1.0644x over previous
#include <cuda_runtime.h>
#include <cuda_bf16.h>
#include <math.h>

#define DD 256
#define NB 3072
#define NCHUNK 8
#define KVSLOT 66560   /* 4*4*64*64 + 4*4*64 */

#define OFF_PROJ  0
#define SZ_PROJ   (8*3*DD*DD)
#define OFF_MERGE (OFF_PROJ + SZ_PROJ)
#define SZ_MERGE  (8*DD*DD)
#define OFF_MLP1  (OFF_MERGE + SZ_MERGE)
#define SZ_MLP1   (8*2*DD*2*DD)
#define OFF_MLP2  (OFF_MLP1 + SZ_MLP1)
#define SZ_MLP2   (8*DD*2*DD)
#define OFF_GAT   (OFF_MLP2 + SZ_MLP2)
#define SZ_GAT    (4*DD*DD)
#define OFF_FIN   (OFF_GAT + SZ_GAT)
#define SZ_FIN    (DD*DD)
#define WTOT      (OFF_FIN + SZ_FIN)

__device__ float g_act[6*DD*NB];
__device__ float g_qkv[(size_t)4*3*DD*NB];
__device__ float g_ob[4*DD*NB];
__device__ float g_msg[4*DD*NB];
__device__ float g_tb[(size_t)4*2*DD*NB];
__device__ float g_agg[2*DD*NB];
__device__ float g_fb[4*DD*NB];
__device__ unsigned short g_fbh[4*DD*NB], g_fbl[4*DD*NB];
__device__ float g_sc[(size_t)2*NB*NB];
__device__ float g_kvpart[NCHUNK*KVSLOT];
__device__ float g_kvred[KVSLOT];
__device__ float g_wa[4*2*DD];
__device__ float g_rmax[2*NB];
__device__ float g_rsum[2*NB];
__device__ float g_cmax[2*NB];
__device__ float g_csum[2*NB];
__device__ int   g_i0[NB];
__device__ int   g_i1[NB];
__device__ int   g_valid0[NB];
__device__ float g_m0[NB];
__device__ float g_m1[NB];
__device__ float g_ms0buf[NB];
__device__ unsigned short g_wbh[WTOT], g_wbl[WTOT];

__device__ __forceinline__ unsigned packbf(float lo, float hi){
    unsigned r; asm("cvt.rn.bf16x2.f32 %0,%1,%2;":"=r"(r):"f"(hi),"f"(lo)); return r;
}
__device__ __forceinline__ unsigned short bf1(float v){
    __nv_bfloat16 b = __float2bfloat16(v);
    return *reinterpret_cast<unsigned short*>(&b);
}
__device__ __forceinline__ float bf2f(unsigned short u){
    return __uint_as_float(((unsigned)u) << 16);
}
__device__ __forceinline__ unsigned prmt(unsigned a, unsigned b, unsigned s){
    unsigned r; asm("prmt.b32 %0,%1,%2,%3;":"=r"(r):"r"(a),"r"(b),"r"(s)); return r;
}
__device__ __forceinline__ void mma16(float* c, const unsigned* a, const unsigned* b){
    asm volatile("mma.sync.aligned.m16n8k16.row.col.f32.bf16.bf16.f32 "
        "{%0,%1,%2,%3}, {%4,%5,%6,%7}, {%8,%9}, {%0,%1,%2,%3};"
        : "+f"(c[0]),"+f"(c[1]),"+f"(c[2]),"+f"(c[3])
        : "r"(a[0]),"r"(a[1]),"r"(a[2]),"r"(a[3]), "r"(b[0]),"r"(b[1]));
}

__global__ void cvt_all(const float* __restrict__ projw, const float* __restrict__ mergew,
                        const float* __restrict__ mlp1w, const float* __restrict__ mlp2w,
                        const float* __restrict__ gatW,  const float* __restrict__ finw,
                        unsigned short* __restrict__ H, unsigned short* __restrict__ L)
{
    int i = blockIdx.x*256 + threadIdx.x;
    if (i >= WTOT/4) return;
    int e = i*4;
    const float* src;
    if      (e < OFF_MERGE) src = projw  + (e - OFF_PROJ);
    else if (e < OFF_MLP1)  src = mergew + (e - OFF_MERGE);
    else if (e < OFF_MLP2)  src = mlp1w  + (e - OFF_MLP1);
    else if (e < OFF_GAT)   src = mlp2w  + (e - OFF_MLP2);
    else if (e < OFF_FIN)   src = gatW   + (e - OFF_GAT);
    else                    src = finw   + (e - OFF_FIN);
    float4 v = *(const float4*)src;
    unsigned h01 = packbf(v.x, v.y), h23 = packbf(v.z, v.w);
    ((uint2*)H)[i] = make_uint2(h01, h23);
    float lx = v.x - __uint_as_float(h01<<16);
    float ly = v.y - __uint_as_float(h01&0xffff0000u);
    float lz = v.z - __uint_as_float(h23<<16);
    float lw = v.w - __uint_as_float(h23&0xffff0000u);
    ((uint2*)L)[i] = make_uint2(packbf(lx,ly), packbf(lz,lw));
}

/* BF16x3 GEMM, templated CTA tile height BM (64 or 128), BN=64, BK=32,
   128 threads (4 warps 2x2), warp tile (BM/2)x32. Double-buffered smem,
   packed B stores, conflict-free strides (A: 20, B: 72). */
template<int BM>
__global__ void __launch_bounds__(128) gemm_tc(
    const unsigned short* __restrict__ Wh, const unsigned short* __restrict__ Wl,
    long long wz, int wtrans, int O,
    const float* __restrict__ Xa, long long xaz,
    const float* __restrict__ Xb, long long xbz, int csplit,
    const float* __restrict__ bias,
    const float* __restrict__ res, long long resz,
    float* __restrict__ Out, long long outz,
    int C, int N, float alpha, int act)
{
    constexpr int MT = BM/32;
    constexpr int AI = BM/8;
    constexpr int AW = BM/16;
    __shared__ unsigned sAh[2][BM][20], sAl[2][BM][20];
    __shared__ unsigned sBh[2][16][72], sBl[2][16][72];
    const int z  = blockIdx.z;
    const int o0 = blockIdx.y * BM, j0 = blockIdx.x * 64;
    const unsigned* WhU = (const unsigned*)(Wh + (size_t)z*(size_t)wz);
    const unsigned* WlU = (const unsigned*)(Wl + (size_t)z*(size_t)wz);
    const float* Xaz = Xa + (size_t)z*(size_t)xaz;
    const float* Xbz = Xb + (size_t)z*(size_t)xbz;
    const int tid  = threadIdx.x;
    const int lane = tid & 31, w = tid >> 5;
    const int wm = w >> 1, wn = w & 1;
    const int g = lane >> 2, t = lane & 3;
    const int C2 = C >> 1, O2 = O >> 1;
    const int bn = tid & 63, cb = (tid >> 6) * 16;

    float acc[MT][4][4];
    #pragma unroll
    for (int i=0;i<MT;i++)
        #pragma unroll
        for (int j=0;j<4;j++)
            #pragma unroll
            for (int k=0;k<4;k++) acc[i][j][k]=0.f;

    unsigned ah0[AI], al0[AI], ah1[AW], al1[AW];
    float bpre[16];

#define B_FLUSH(bu) do {                                                      \
    _Pragma("unroll")                                                         \
    for (int jj2 = 0; jj2 < 8; jj2++) {                                       \
        float v0 = bpre[2*jj2], v1 = bpre[2*jj2+1];                           \
        unsigned hw = packbf(v0, v1);                                         \
        float h0 = __uint_as_float(hw << 16);                                 \
        float h1 = __uint_as_float(hw & 0xffff0000u);                         \
        unsigned lw = packbf(v0 - h0, v1 - h1);                               \
        int p = (cb >> 1) + jj2;                                              \
        sBh[bu][p][bn] = hw;                                                  \
        sBl[bu][p][bn] = lw;                                                  \
    }                                                                         \
} while(0)

    if (!wtrans) {
        #pragma unroll
        for (int i = 0; i < AI; i++) {
            int idx = tid + i*128;
            int o = idx >> 4, p = idx & 15;
            size_t a = (size_t)(o0+o)*C2 + p;
            ah0[i] = WhU[a]; al0[i] = WlU[a];
        }
    } else {
        #pragma unroll
        for (int i = 0; i < AW; i++) {
            int idx = tid + i*128;
            int p = idx & 15, op = idx >> 4;
            size_t r0 = (size_t)(2*p)*O2 + ((o0 + 2*op) >> 1);
            ah0[i] = WhU[r0]; ah1[i] = WhU[r0 + O2];
            al0[i] = WlU[r0]; al1[i] = WlU[r0 + O2];
        }
    }
    #pragma unroll
    for (int i = 0; i < 16; i++) {
        int c = cb + i;
        const float* xp = (c < csplit) ? Xaz + (size_t)c*N
                                       : Xbz + (size_t)(c-csplit)*N;
        bpre[i] = xp[j0 + bn];
    }
    if (!wtrans) {
        #pragma unroll
        for (int i = 0; i < AI; i++) {
            int idx = tid + i*128;
            int o = idx >> 4, p = idx & 15;
            sAh[0][o][p] = ah0[i]; sAl[0][o][p] = al0[i];
        }
    } else {
        #pragma unroll
        for (int i = 0; i < AW; i++) {
            int idx = tid + i*128;
            int p = idx & 15, op = idx >> 4, o = 2*op;
            sAh[0][o][p]   = prmt(ah0[i], ah1[i], 0x5410);
            sAh[0][o+1][p] = prmt(ah0[i], ah1[i], 0x7632);
            sAl[0][o][p]   = prmt(al0[i], al1[i], 0x5410);
            sAl[0][o+1][p] = prmt(al0[i], al1[i], 0x7632);
        }
    }
    B_FLUSH(0);
    __syncthreads();

    const int ntiles = C >> 5;
    for (int kt = 0; kt < ntiles; kt++) {
        const int cur = kt & 1, nxt = cur ^ 1;
        const bool more = (kt + 1 < ntiles);
        if (more) {
            int k0 = (kt + 1) << 5;
            if (!wtrans) {
                #pragma unroll
                for (int i = 0; i < AI; i++) {
                    int idx = tid + i*128;
                    int o = idx >> 4, p = idx & 15;
                    size_t a = (size_t)(o0+o)*C2 + (k0>>1) + p;
                    ah0[i] = WhU[a]; al0[i] = WlU[a];
                }
            } else {
                #pragma unroll
                for (int i = 0; i < AW; i++) {
                    int idx = tid + i*128;
                    int p = idx & 15, op = idx >> 4;
                    size_t r0 = (size_t)(k0 + 2*p)*O2 + ((o0 + 2*op) >> 1);
                    ah0[i] = WhU[r0]; ah1[i] = WhU[r0 + O2];
                    al0[i] = WlU[r0]; al1[i] = WlU[r0 + O2];
                }
            }
            #pragma unroll
            for (int i = 0; i < 16; i++) {
                int cg = k0 + cb + i;
                const float* xp = (cg < csplit) ? Xaz + (size_t)cg*N
                                                : Xbz + (size_t)(cg-csplit)*N;
                bpre[i] = xp[j0 + bn];
            }
        }
        #pragma unroll
        for (int s = 0; s < 2; s++) {
            int s8 = s*8;
            unsigned ah[MT][4], al[MT][4], bh[4][2], bl[4][2];
            #pragma unroll
            for (int mt = 0; mt < MT; mt++) {
                int r0 = wm*(BM/2) + mt*16 + g;
                ah[mt][0]=sAh[cur][r0][s8+t];    al[mt][0]=sAl[cur][r0][s8+t];
                ah[mt][1]=sAh[cur][r0+8][s8+t];  al[mt][1]=sAl[cur][r0+8][s8+t];
                ah[mt][2]=sAh[cur][r0][s8+t+4];  al[mt][2]=sAl[cur][r0][s8+t+4];
                ah[mt][3]=sAh[cur][r0+8][s8+t+4];al[mt][3]=sAl[cur][r0+8][s8+t+4];
            }
            #pragma unroll
            for (int nt = 0; nt < 4; nt++) {
                int cc = wn*32 + nt*8 + g;
                bh[nt][0]=sBh[cur][s8+t][cc];   bl[nt][0]=sBl[cur][s8+t][cc];
                bh[nt][1]=sBh[cur][s8+t+4][cc]; bl[nt][1]=sBl[cur][s8+t+4][cc];
            }
            #pragma unroll
            for (int mt = 0; mt < MT; mt++)
                #pragma unroll
                for (int nt = 0; nt < 4; nt++) {
                    mma16(acc[mt][nt], ah[mt], bh[nt]);
                    mma16(acc[mt][nt], ah[mt], bl[nt]);
                    mma16(acc[mt][nt], al[mt], bh[nt]);
                }
        }
        if (more) {
            if (!wtrans) {
                #pragma unroll
                for (int i = 0; i < AI; i++) {
                    int idx = tid + i*128;
                    int o = idx >> 4, p = idx & 15;
                    sAh[nxt][o][p] = ah0[i]; sAl[nxt][o][p] = al0[i];
                }
            } else {
                #pragma unroll
                for (int i = 0; i < AW; i++) {
                    int idx = tid + i*128;
                    int p = idx & 15, op = idx >> 4, o = 2*op;
                    sAh[nxt][o][p]   = prmt(ah0[i], ah1[i], 0x5410);
                    sAh[nxt][o+1][p] = prmt(ah0[i], ah1[i], 0x7632);
                    sAl[nxt][o][p]   = prmt(al0[i], al1[i], 0x5410);
                    sAl[nxt][o+1][p] = prmt(al0[i], al1[i], 0x7632);
                }
            }
            B_FLUSH(nxt);
        }
        __syncthreads();
    }
    #pragma unroll
    for (int mt = 0; mt < MT; mt++) {
        #pragma unroll
        for (int nt = 0; nt < 4; nt++) {
            int row0 = o0 + wm*(BM/2) + mt*16 + g;
            int col0 = j0 + wn*32 + nt*8 + 2*t;
            #pragma unroll
            for (int e = 0; e < 4; e++) {
                int o  = row0 + (e >> 1)*8;
                int jj = col0 + (e & 1);
                float v = acc[mt][nt][e]*alpha + (bias ? bias[o] : 0.f);
                if (act == 2) v = v > 0.f ? v : (__expf(v) - 1.f);
                size_t off = (size_t)z*(size_t)outz + (size_t)o*N + jj;
                if (res) v += res[(size_t)z*(size_t)resz + (size_t)o*N + jj];
                Out[off] = v;
            }
        }
    }
#undef B_FLUSH
}

/* linear attention stage 1: z in 0..3 pseudo-batch (stream x batch) */
__global__ void __launch_bounds__(256) attn_kv_kernel(
    const float* __restrict__ K, long long kz,
    const float* __restrict__ V, long long vz,
    float* __restrict__ part, int ns)
{
    int chunk = blockIdx.x, h = blockIdx.y, z = blockIdx.z;
    int mlen = ns / NCHUNK, m0 = chunk * mlen;
    const float* Kb = K + (size_t)z*(size_t)kz;
    const float* Vb = V + (size_t)z*(size_t)vz;
    __shared__ float ks[64][33];
    __shared__ float vs[64][33];
    int tid = threadIdx.x;
    int qi0 = (tid>>4)*4, ki0 = (tid&15)*4;
    float acc[4][4]={{0,0,0,0},{0,0,0,0},{0,0,0,0},{0,0,0,0}};
    float ksum = 0.f, invm = 1.f/(float)ns;
    for (int mt = 0; mt < mlen; mt += 32) {
        __syncthreads();
        for (int idx = tid; idx < 64*32; idx += 256) {
            int d = idx>>5, mm = idx&31, m = m0+mt+mm;
            float kr = Kb[(size_t)(d*4+h)*ns + m];
            ks[d][mm] = kr>0.f ? kr+1.f : __expf(kr);
            vs[d][mm] = Vb[(size_t)(d*4+h)*ns + m]*invm;
        }
        __syncthreads();
        if (tid < 64) {
            #pragma unroll
            for (int mm=0;mm<32;mm++) ksum += ks[tid][mm];
        }
        #pragma unroll 4
        for (int mm=0;mm<32;mm++){
            float vv[4], kv[4];
            #pragma unroll
            for (int i=0;i<4;i++) vv[i]=vs[qi0+i][mm];
            #pragma unroll
            for (int j=0;j<4;j++) kv[j]=ks[ki0+j][mm];
            #pragma unroll
            for (int i=0;i<4;i++)
                #pragma unroll
                for (int j=0;j<4;j++) acc[i][j]+=vv[i]*kv[j];
        }
    }
    float* dst = part + (size_t)chunk*KVSLOT;
    size_t base = (size_t)(z*4+h)*64;
    #pragma unroll
    for (int i=0;i<4;i++)
        #pragma unroll
        for (int j=0;j<4;j++)
            dst[(base+qi0+i)*64 + ki0+j] = acc[i][j];
    if (tid < 64) dst[65536 + base + tid] = ksum;
}

__global__ void kv_reduce_kernel(const float* __restrict__ part, float* __restrict__ o)
{
    int i = blockIdx.x*256 + threadIdx.x;
    if (i < KVSLOT) {
        float s = 0.f;
        #pragma unroll
        for (int c=0;c<NCHUNK;c++) s += part[(size_t)c*KVSLOT + i];
        o[i] = s;
    }
}

__global__ void __launch_bounds__(128) attn_out_kernel(
    const float* __restrict__ Q, long long qz, const float* __restrict__ KVr,
    float* __restrict__ O_, long long oz, int nq, int ns)
{
    int z = blockIdx.z, h = blockIdx.y;
    int m = blockIdx.x*128 + threadIdx.x;
    __shared__ float kvs[64][64];
    __shared__ float kss[64];
    const float* src = KVr + (size_t)(z*4+h)*4096;
    for (int i = threadIdx.x; i < 4096; i += 128) kvs[i>>6][i&63] = src[i];
    if (threadIdx.x < 64) kss[threadIdx.x] = KVr[65536 + (size_t)(z*4+h)*64 + threadIdx.x];
    __syncthreads();
    const float* Qb = Q + (size_t)z*(size_t)qz;
    float qv[64], denom = 0.f;
    #pragma unroll
    for (int d=0;d<64;d++){
        float q = Qb[(size_t)(d*4+h)*nq + m];
        q = q>0.f ? q+1.f : __expf(q);
        qv[d]=q; denom += q*kss[d];
    }
    float zf = (float)ns/(denom + 1e-6f);
    float* Ob = O_ + (size_t)z*(size_t)oz;
    for (int qd=0; qd<64; qd++){
        float accv = 0.f;
        #pragma unroll
        for (int d=0;d<64;d++) accv += qv[d]*kvs[qd][d];
        Ob[(size_t)(qd*4+h)*nq + m] = accv*zf;
    }
}

__global__ void __launch_bounds__(256) instnorm_relu_kernel(float* X, int C, int n)
{
    int c = blockIdx.x, b = blockIdx.y;
    float* row = X + ((size_t)b*C + c)*n;
    int tid = threadIdx.x;
    float s=0.f, s2=0.f;
    for (int i=tid;i<n;i+=256){ float v=row[i]; s+=v; s2+=v*v; }
    __shared__ float sm1[256], sm2[256];
    sm1[tid]=s; sm2[tid]=s2; __syncthreads();
    for (int st=128;st;st>>=1){
        if (tid<st){ sm1[tid]+=sm1[tid+st]; sm2[tid]+=sm2[tid+st]; }
        __syncthreads();
    }
    float mean = sm1[0]/(float)n;
    float var = sm2[0]/(float)n - mean*mean;
    float rstd = rsqrtf(var + 1e-5f);
    for (int i=tid;i<n;i+=256){
        float v = (row[i]-mean)*rstd;
        row[i] = v>0.f ? v : 0.f;
    }
}

__global__ void gat_vec_kernel(const float* __restrict__ gatW,
                               const float* __restrict__ gata, float* __restrict__ wa)
{
    int gg = blockIdx.x, d = threadIdx.x;
    const float* W = gatW + (size_t)gg*DD*DD;
    const float* a = gata + (size_t)gg*2*DD;
    float s1=0.f, s2=0.f;
    for (int o=0;o<DD;o++){ float w=W[(size_t)d*DD+o]; s1+=w*a[o]; s2+=w*a[DD+o]; }
    wa[gg*2*DD + d] = s1;
    wa[gg*2*DD + DD + d] = s2;
}

__global__ void __launch_bounds__(256) gat_agg_kernel(
    const float* __restrict__ d3, const float* __restrict__ d2d,
    const float* __restrict__ wa, float* __restrict__ agg, int n)
{
    int b = blockIdx.y;
    int warp = threadIdx.x>>5, lane = threadIdx.x&31;
    int nn = blockIdx.x*8 + warp;
    const float* Wa1 = wa;
    const float* Wa2 = wa + DD;
    const float* d3b = d3 + (size_t)b*DD*n;
    const float* d2b = d2d + (size_t)b*DD*(size_t)n*8;
    size_t n8 = (size_t)n*8;
    float x3[8], w2v[8];
    float sself=0.f, s0=0.f;
    #pragma unroll
    for (int r=0;r<8;r++){
        int d = lane + r*32;
        x3[r]=d3b[(size_t)d*n+nn]; w2v[r]=Wa2[d];
        sself += x3[r]*Wa1[d]; s0 += x3[r]*w2v[r];
    }
    #pragma unroll
    for (int off=16;off;off>>=1){
        sself += __shfl_xor_sync(0xffffffffu, sself, off);
        s0    += __shfl_xor_sync(0xffffffffu, s0, off);
    }
    float e[9]; e[0] = sself + s0;
    size_t nbase = (size_t)nn*8;
    #pragma unroll
    for (int l=1;l<9;l++){
        float sl = 0.f;
        #pragma unroll
        for (int r=0;r<8;r++)
            sl += d2b[(size_t)(lane+r*32)*n8 + nbase + (l-1)] * w2v[r];
        #pragma unroll
        for (int off=16;off;off>>=1) sl += __shfl_xor_sync(0xffffffffu, sl, off);
        e[l] = sself + sl;
    }
    float mx = -1e30f;
    #pragma unroll
    for (int l=0;l<9;l++){ e[l] = e[l]>0.f ? e[l] : 0.2f*e[l]; mx = fmaxf(mx, e[l]); }
    float sum = 0.f;
    #pragma unroll
    for (int l=0;l<9;l++){ e[l] = __expf(e[l]-mx); sum += e[l]; }
    float inv = 1.f/sum;
    float accv[8];
    #pragma unroll
    for (int r=0;r<8;r++) accv[r] = e[0]*inv*x3[r];
    #pragma unroll
    for (int l=1;l<9;l++){
        float al = e[l]*inv;
        #pragma unroll
        for (int r=0;r<8;r++)
            accv[r] += al * d2b[(size_t)(lane+r*32)*n8 + nbase + (l-1)];
    }
    float* ab = agg + (size_t)b*DD*n;
    #pragma unroll
    for (int r=0;r<8;r++) ab[(size_t)(lane+r*32)*n + nn] = accv[r];
}

__global__ void colnorm_kernel(float* X, unsigned short* H, unsigned short* L, int n)
{
    int b = blockIdx.y;
    int col = blockIdx.x*256 + threadIdx.x;
    size_t zb = (size_t)b*DD*n;
    float* Xb = X + zb;
    float s = 0.f;
    for (int d=0;d<DD;d++){ float v=Xb[(size_t)d*n+col]; s += v*v; }
    float inv = 1.f / fmaxf(sqrtf(s), 1e-12f);
    for (int d=0;d<DD;d++){
        float v = Xb[(size_t)d*n+col]*inv;
        Xb[(size_t)d*n+col] = v;
        unsigned short hb = bf1(v);
        H[zb + (size_t)d*n + col] = hb;
        L[zb + (size_t)d*n + col] = bf1(v - bf2f(hb));
    }
}

__global__ void __launch_bounds__(256) row_stats_kernel(
    const float* __restrict__ S, float* rmax, float* rsum, int n1, int n2)
{
    int br = blockIdx.y*n1 + blockIdx.x;
    const float* row = S + (size_t)br*n2;
    int tid = threadIdx.x;
    __shared__ float sm[256];
    float mx = -1e30f;
    for (int j=tid;j<n2;j+=256) mx = fmaxf(mx, row[j]);
    sm[tid]=mx; __syncthreads();
    for (int st=128;st;st>>=1){ if (tid<st) sm[tid]=fmaxf(sm[tid],sm[tid+st]); __syncthreads(); }
    mx = sm[0]; __syncthreads();
    float s = 0.f;
    for (int j=tid;j<n2;j+=256) s += __expf(row[j]-mx);
    sm[tid]=s; __syncthreads();
    for (int st=128;st;st>>=1){ if (tid<st) sm[tid]+=sm[tid+st]; __syncthreads(); }
    if (tid==0){ rmax[br]=mx; rsum[br]=sm[0]; }
}

__global__ void col_stats_kernel(const float* __restrict__ S,
                                 float* cmax, float* csum, int n1, int n2)
{
    int b = blockIdx.y;
    int c = blockIdx.x*256 + threadIdx.x;
    const float* Sb = S + (size_t)b*n1*n2;
    float mx = -1e30f, s = 0.f;
    for (int r=0;r<n1;r++){
        float v = Sb[(size_t)r*n2 + c];
        if (v > mx){ s = s*__expf(mx-v) + 1.f; mx = v; }
        else s += __expf(v-mx);
    }
    cmax[b*n1 + c] = mx;
    csum[b*n1 + c] = s;
}

__global__ void conf_kernel(const float* __restrict__ S,
    const float* __restrict__ rmax, const float* __restrict__ rsum,
    const float* __restrict__ cmax, const float* __restrict__ csum,
    float* __restrict__ conf)
{
    size_t idx = (size_t)blockIdx.x*256 + threadIdx.x;
    int z = (int)(idx / ((size_t)NB*NB));
    size_t rem = idx - (size_t)z*NB*NB;
    int n = (int)(rem / NB), m = (int)(rem % NB);
    float s = S[idx];
    conf[idx] = __expf(2.f*s - rmax[z*NB+n] - cmax[z*NB+m])
                / (rsum[z*NB+n]*csum[z*NB+m]);
}

__global__ void __launch_bounds__(256) rowargmax_kernel(
    const float* __restrict__ conf0, int* i0, float* m0)
{
    int n = blockIdx.x;
    const float* row = conf0 + (size_t)n*NB;
    int tid = threadIdx.x;
    float best = -1e30f; int bidx = 0;
    for (int m=tid;m<NB;m+=256){ float v=row[m]; if (v>best){best=v;bidx=m;} }
    __shared__ float bv[256]; __shared__ int bi[256];
    bv[tid]=best; bi[tid]=bidx; __syncthreads();
    for (int st=128;st;st>>=1){
        if (tid<st){
            if (bv[tid+st]>bv[tid] || (bv[tid+st]==bv[tid] && bi[tid+st]<bi[tid])){
                bv[tid]=bv[tid+st]; bi[tid]=bi[tid+st];
            }
        }
        __syncthreads();
    }
    if (tid==0){ i0[n]=bi[0]; m0[n]=bv[0]; }
}

__global__ void colargmax_kernel(const float* __restrict__ conf0, int* i1, float* m1)
{
    int m = blockIdx.x*256 + threadIdx.x;
    float best = -1e30f; int bidx = 0;
    for (int n=0;n<NB;n++){
        float v = conf0[(size_t)n*NB + m];
        if (v > best){ best=v; bidx=n; }
    }
    i1[m]=bidx; m1[m]=best;
}

__global__ void match0_kernel(const int* i0, const int* i1, const float* m0,
                              float* out, float* ms0buf, int* valid0)
{
    int n = blockIdx.x*256 + threadIdx.x;
    int t = i0[n];
    int mutual = (i1[t] == n);
    float ms0 = mutual ? m0[n] : 0.f;
    int v0 = mutual && (ms0 > 0.2f);
    out[n] = v0 ? (float)t : -1.f;
    out[2*NB + n] = ms0;
    ms0buf[n] = ms0;
    valid0[n] = v0;
}

__global__ void match1_kernel(const int* i0, const int* i1,
                              const float* ms0buf, const int* valid0, float* out)
{
    int m = blockIdx.x*256 + threadIdx.x;
    int t = i1[m];
    int mutual = (i0[t] == m);
    float ms1 = mutual ? ms0buf[t] : 0.f;
    int v1 = mutual && valid0[t];
    out[NB + m] = v1 ? (float)t : -1.f;
    out[3*NB + m] = ms1;
}

/* --------------------------------- host ---------------------------------- */
static void* gsym(const void* s){ void* p=nullptr; cudaGetSymbolAddress(&p, s); return p; }
typedef unsigned short u16;

extern "C" void kernel_launch(void* const* d_in, const int* in_sizes, int n_in,
                              void* d_out, int out_size)
{
    const float* in_dq   = (const float*)d_in[0];
    const float* in_d3   = (const float*)d_in[1];
    const float* in_d2db = (const float*)d_in[2];
    const float* projb   = (const float*)d_in[4];
    const float* mergeb  = (const float*)d_in[6];
    const float* mlp1b   = (const float*)d_in[8];
    const float* mlp2b   = (const float*)d_in[10];
    const float* gatW    = (const float*)d_in[11];
    const float* gata    = (const float*)d_in[12];
    const float* finb    = (const float*)d_in[14];
    float* out = (float*)d_out;

    float* act    = (float*)gsym(g_act);
    float* qkv    = (float*)gsym(g_qkv);
    float* ob     = (float*)gsym(g_ob);
    float* msg    = (float*)gsym(g_msg);
    float* tb     = (float*)gsym(g_tb);
    float* agg    = (float*)gsym(g_agg);
    float* fb     = (float*)gsym(g_fb);
    u16*   fbh    = (u16*)gsym(g_fbh);
    u16*   fbl    = (u16*)gsym(g_fbl);
    float* sc     = (float*)gsym(g_sc);
    float* kvpart = (float*)gsym(g_kvpart);
    float* kvred  = (float*)gsym(g_kvred);
    float* wa     = (float*)gsym(g_wa);
    float* rmax   = (float*)gsym(g_rmax);
    float* rsum   = (float*)gsym(g_rsum);
    float* cmax   = (float*)gsym(g_cmax);
    float* csum   = (float*)gsym(g_csum);
    int*   i0     = (int*)gsym(g_i0);
    int*   i1     = (int*)gsym(g_i1);
    int*   valid0 = (int*)gsym(g_valid0);
    float* m0     = (float*)gsym(g_m0);
    float* m1     = (float*)gsym(g_m1);
    float* ms0buf = (float*)gsym(g_ms0buf);
    u16*   wbh    = (u16*)gsym(g_wbh);
    u16*   wbl    = (u16*)gsym(g_wbl);

    const int N = NB;
    const long long DN  = (long long)DD*N;
    const long long QKN = (long long)3*DD*N;
    const long long TBN = (long long)2*DD*N;
    float* dqp = act;
    float* d3p = act + 2*DN;
    float* dqo = act + 4*DN;

    cvt_all<<<(WTOT/4+255)/256,256>>>((const float*)d_in[3], (const float*)d_in[5],
                                      (const float*)d_in[7], (const float*)d_in[9],
                                      gatW, (const float*)d_in[13], wbh, wbl);

    cudaMemcpyAsync(dqp, in_dq, (size_t)2*DN*sizeof(float), cudaMemcpyDeviceToDevice);
    cudaMemcpyAsync(d3p, in_d3, (size_t)2*DN*sizeof(float), cudaMemcpyDeviceToDevice);
    gat_vec_kernel<<<4,256>>>(gatW, gata, wa);

    int gi = 0, ai = 0;
    for (int step = 0; step < 12; step++) {
        int t = step % 3;
        if (t == 0) {
            gat_agg_kernel<<<dim3(N/8,2),256>>>(d3p, in_d2db, wa + gi*2*DD, agg, N);
            gemm_tc<64><<<dim3(N/64,4,2),128>>>(wbh+OFF_GAT+(size_t)gi*DD*DD,
                wbl+OFF_GAT+(size_t)gi*DD*DD, 0,1,DD,
                agg, DN, agg, DN, DD, nullptr, nullptr,0,
                d3p, DN, DD, N, 1.f, 2);
            gi++;
        } else {
            const u16* pwh = wbh + OFF_PROJ + (size_t)ai*3*DD*DD;
            const u16* pwl = wbl + OFF_PROJ + (size_t)ai*3*DD*DD;
            const float* pb = projb + (size_t)ai*3*DD;
            if (t == 1) {
                gemm_tc<128><<<dim3(N/64,6,4),128>>>(pwh, pwl, 0,0,768,
                    act, DN, act, DN, DD, pb, nullptr,0, qkv, QKN, DD, N, 1.f, 0);
            } else {
                cudaMemcpyAsync(dqo, dqp, (size_t)2*DN*sizeof(float),
                                cudaMemcpyDeviceToDevice);
                gemm_tc<128><<<dim3(N/64,2,4),128>>>(pwh, pwl, 0,0,DD,
                    act, DN, act, DN, DD, pb, nullptr,0, qkv, QKN, DD, N, 1.f, 0);
                gemm_tc<128><<<dim3(N/64,4,4),128>>>(pwh+DD*DD, pwl+DD*DD, 0,0,512,
                    d3p, DN, d3p, DN, DD, pb+DD, nullptr,0,
                    qkv + (size_t)DD*N, QKN, DD, N, 1.f, 0);
            }
            attn_kv_kernel<<<dim3(NCHUNK,4,4),256>>>(qkv + (size_t)DD*N, QKN,
                                                     qkv + (size_t)2*DD*N, QKN,
                                                     kvpart, N);
            kv_reduce_kernel<<<(KVSLOT+255)/256,256>>>(kvpart, kvred);
            attn_out_kernel<<<dim3(N/128,4,4),128>>>(qkv, QKN, kvred, ob, DN, N, N);
            gemm_tc<128><<<dim3(N/64,2,4),128>>>(wbh+OFF_MERGE+(size_t)ai*DD*DD,
                wbl+OFF_MERGE+(size_t)ai*DD*DD, 0,0,DD,
                ob, DN, ob, DN, DD, mergeb+(size_t)ai*DD, nullptr,0,
                msg, DN, DD, N, 1.f, 0);
            gemm_tc<128><<<dim3(N/64,4,4),128>>>(wbh+OFF_MLP1+(size_t)ai*512*512,
                wbl+OFF_MLP1+(size_t)ai*512*512, 0,0,512,
                act, DN, msg, DN, DD, mlp1b+(size_t)ai*512, nullptr,0,
                tb, TBN, 512, N, 1.f, 0);
            instnorm_relu_kernel<<<dim3(512,4),256>>>(tb, 512, N);
            gemm_tc<128><<<dim3(N/64,2,4),128>>>(wbh+OFF_MLP2+(size_t)ai*DD*512,
                wbl+OFF_MLP2+(size_t)ai*DD*512, 0,0,DD,
                tb, TBN, tb, TBN, 512, mlp2b+(size_t)ai*DD, act, DN,
                act, DN, 512, N, 1.f, 0);
            ai++;
        }
    }

    gemm_tc<128><<<dim3(N/64,2,4),128>>>(wbh+OFF_FIN, wbl+OFF_FIN, 0,0,DD,
        act, DN, act, DN, DD, finb, nullptr,0, fb, DN, DD, N, 1.f, 0);
    colnorm_kernel<<<dim3(N/256,4),256>>>(fb, fbh, fbl, N);

    gemm_tc<128><<<dim3(N/64,N/128,2),128>>>(fbh, fbl, DN, 1, N,
        fb + 2*DN, DN, fb + 2*DN, DN, DD,
        nullptr, nullptr,0, sc, (long long)N*N, DD, N, 10.f, 0);
    row_stats_kernel<<<dim3(N,2),256>>>(sc, rmax, rsum, N, N);
    col_stats_kernel<<<dim3(N/256,2),256>>>(sc, cmax, csum, N, N);

    float* conf = out + 4*NB;
    conf_kernel<<<(unsigned)((size_t)2*N*N/256),256>>>(sc, rmax, rsum, cmax, csum, conf);
    rowargmax_kernel<<<N,256>>>(conf, i0, m0);
    colargmax_kernel<<<N/256,256>>>(conf, i1, m1);
    match0_kernel<<<N/256,256>>>(i0, i1, m0, out, ms0buf, valid0);
    match1_kernel<<<N/256,256>>>(i0, i1, ms0buf, valid0, out);
}

// round 14
// speedup vs baseline: 1.1692x; 1.0985x over previous
#include <cuda_runtime.h>
#include <cuda_bf16.h>
#include <math.h>

#define DD 256
#define NB 3072
#define NCHUNK 8
#define KVSLOT 66560   /* 4*4*64*64 + 4*4*64 */

#define OFF_PROJ  0
#define SZ_PROJ   (8*3*DD*DD)
#define OFF_MERGE (OFF_PROJ + SZ_PROJ)
#define SZ_MERGE  (8*DD*DD)
#define OFF_MLP1  (OFF_MERGE + SZ_MERGE)
#define SZ_MLP1   (8*2*DD*2*DD)
#define OFF_MLP2  (OFF_MLP1 + SZ_MLP1)
#define SZ_MLP2   (8*DD*2*DD)
#define OFF_GAT   (OFF_MLP2 + SZ_MLP2)
#define SZ_GAT    (4*DD*DD)
#define OFF_FIN   (OFF_GAT + SZ_GAT)
#define SZ_FIN    (DD*DD)
#define WTOT      (OFF_FIN + SZ_FIN)

__device__ float g_act[6*DD*NB];
__device__ float g_qkv[(size_t)4*3*DD*NB];
__device__ float g_ob[4*DD*NB];
__device__ float g_msg[4*DD*NB];
__device__ float g_tb[(size_t)4*2*DD*NB];
__device__ float g_agg[2*DD*NB];
__device__ float g_fb[4*DD*NB];
__device__ unsigned short g_fbh[4*DD*NB], g_fbl[4*DD*NB];
__device__ float g_sc[(size_t)2*NB*NB];
__device__ float g_kvpart[NCHUNK*KVSLOT];
__device__ float g_kvred[KVSLOT];
__device__ float g_wa[4*2*DD];
__device__ float g_rmax[2*NB];
__device__ float g_rsum[2*NB];
__device__ float g_cmax[2*NB];
__device__ float g_csum[2*NB];
__device__ int   g_i0[NB];
__device__ int   g_i1[NB];
__device__ int   g_valid0[NB];
__device__ float g_m0[NB];
__device__ float g_m1[NB];
__device__ float g_ms0buf[NB];
__device__ unsigned short g_wbh[WTOT], g_wbl[WTOT];

__device__ __forceinline__ unsigned packbf(float lo, float hi){
    unsigned r; asm("cvt.rn.bf16x2.f32 %0,%1,%2;":"=r"(r):"f"(hi),"f"(lo)); return r;
}
__device__ __forceinline__ unsigned short bf1(float v){
    __nv_bfloat16 b = __float2bfloat16(v);
    return *reinterpret_cast<unsigned short*>(&b);
}
__device__ __forceinline__ float bf2f(unsigned short u){
    return __uint_as_float(((unsigned)u) << 16);
}
__device__ __forceinline__ unsigned prmt(unsigned a, unsigned b, unsigned s){
    unsigned r; asm("prmt.b32 %0,%1,%2,%3;":"=r"(r):"r"(a),"r"(b),"r"(s)); return r;
}
__device__ __forceinline__ void mma16(float* c, const unsigned* a, const unsigned* b){
    asm volatile("mma.sync.aligned.m16n8k16.row.col.f32.bf16.bf16.f32 "
        "{%0,%1,%2,%3}, {%4,%5,%6,%7}, {%8,%9}, {%0,%1,%2,%3};"
        : "+f"(c[0]),"+f"(c[1]),"+f"(c[2]),"+f"(c[3])
        : "r"(a[0]),"r"(a[1]),"r"(a[2]),"r"(a[3]), "r"(b[0]),"r"(b[1]));
}
__device__ __forceinline__ void cpa16(unsigned dst, const void* src){
    asm volatile("cp.async.ca.shared.global [%0], [%1], 16;"
                 :: "r"(dst), "l"(src));
}
__device__ __forceinline__ unsigned s2u(const void* p){
    return (unsigned)__cvta_generic_to_shared(p);
}

__global__ void cvt_all(const float* __restrict__ projw, const float* __restrict__ mergew,
                        const float* __restrict__ mlp1w, const float* __restrict__ mlp2w,
                        const float* __restrict__ gatW,  const float* __restrict__ finw,
                        unsigned short* __restrict__ H, unsigned short* __restrict__ L)
{
    int i = blockIdx.x*256 + threadIdx.x;
    if (i >= WTOT/4) return;
    int e = i*4;
    const float* src;
    if      (e < OFF_MERGE) src = projw  + (e - OFF_PROJ);
    else if (e < OFF_MLP1)  src = mergew + (e - OFF_MERGE);
    else if (e < OFF_MLP2)  src = mlp1w  + (e - OFF_MLP1);
    else if (e < OFF_GAT)   src = mlp2w  + (e - OFF_MLP2);
    else if (e < OFF_FIN)   src = gatW   + (e - OFF_GAT);
    else                    src = finw   + (e - OFF_FIN);
    float4 v = *(const float4*)src;
    unsigned h01 = packbf(v.x, v.y), h23 = packbf(v.z, v.w);
    ((uint2*)H)[i] = make_uint2(h01, h23);
    float lx = v.x - __uint_as_float(h01<<16);
    float ly = v.y - __uint_as_float(h01&0xffff0000u);
    float lz = v.z - __uint_as_float(h23<<16);
    float lw = v.w - __uint_as_float(h23&0xffff0000u);
    ((uint2*)L)[i] = make_uint2(packbf(lx,ly), packbf(lz,lw));
}

/* BF16x3 GEMM. BM templated (64/128); WT templated (0: A via cp.async,
   1: A transposed via register+prmt). BN=64, BK=32, 128 threads (2x2 warps),
   warp tile (BM/2)x32. Double-buffered smem, packed B stores, strides 20/72. */
template<int BM, int WT>
__global__ void __launch_bounds__(128) gemm_tc(
    const unsigned short* __restrict__ Wh, const unsigned short* __restrict__ Wl,
    long long wz, int O,
    const float* __restrict__ Xa, long long xaz,
    const float* __restrict__ Xb, long long xbz, int csplit,
    const float* __restrict__ bias,
    const float* __restrict__ res, long long resz,
    float* __restrict__ Out, long long outz,
    int C, int N, float alpha, int act)
{
    constexpr int MT = BM/32;
    constexpr int AW = BM/16;
    __shared__ unsigned sAh[2][BM][20], sAl[2][BM][20];
    __shared__ unsigned sBh[2][16][72], sBl[2][16][72];
    const int z  = blockIdx.z;
    const int o0 = blockIdx.y * BM, j0 = blockIdx.x * 64;
    const unsigned* WhU = (const unsigned*)(Wh + (size_t)z*(size_t)wz);
    const unsigned* WlU = (const unsigned*)(Wl + (size_t)z*(size_t)wz);
    const float* Xaz = Xa + (size_t)z*(size_t)xaz;
    const float* Xbz = Xb + (size_t)z*(size_t)xbz;
    const int tid  = threadIdx.x;
    const int lane = tid & 31, w = tid >> 5;
    const int wm = w >> 1, wn = w & 1;
    const int g = lane >> 2, t = lane & 3;
    const int C2 = C >> 1, O2 = O >> 1;
    const int bn = tid & 63, cb = (tid >> 6) * 16;

    float acc[MT][4][4];
    #pragma unroll
    for (int i=0;i<MT;i++)
        #pragma unroll
        for (int j=0;j<4;j++)
            #pragma unroll
            for (int k=0;k<4;k++) acc[i][j][k]=0.f;

    unsigned ah0[WT ? AW : 1], al0[WT ? AW : 1];
    unsigned ah1[WT ? AW : 1], al1[WT ? AW : 1];
    float bpre[16];

#define B_FLUSH(bu) do {                                                      \
    _Pragma("unroll")                                                         \
    for (int jj2 = 0; jj2 < 8; jj2++) {                                       \
        float v0 = bpre[2*jj2], v1 = bpre[2*jj2+1];                           \
        unsigned hw = packbf(v0, v1);                                         \
        float h0 = __uint_as_float(hw << 16);                                 \
        float h1 = __uint_as_float(hw & 0xffff0000u);                         \
        unsigned lw = packbf(v0 - h0, v1 - h1);                               \
        int p = (cb >> 1) + jj2;                                              \
        sBh[bu][p][bn] = hw;                                                  \
        sBl[bu][p][bn] = lw;                                                  \
    }                                                                         \
} while(0)

/* async copy A tile (k word offset kw) into buffer bu; WT==0 only */
#define A_CPASYNC(bu, kw) do {                                                \
    _Pragma("unroll")                                                         \
    for (int i = 0; i < BM/32; i++) {                                         \
        int idx = tid + i*128;                                                \
        int o = idx >> 2, p4 = (idx & 3) * 4;                                 \
        cpa16(s2u(&sAh[bu][o][p4]), WhU + (size_t)(o0+o)*C2 + (kw) + p4);     \
        cpa16(s2u(&sAl[bu][o][p4]), WlU + (size_t)(o0+o)*C2 + (kw) + p4);     \
    }                                                                         \
    asm volatile("cp.async.commit_group;");                                   \
} while(0)

/* register load + prmt store of transposed A tile; WT==1 only */
#define A_WT_LOAD(k0) do {                                                    \
    _Pragma("unroll")                                                         \
    for (int i = 0; i < AW; i++) {                                            \
        int idx = tid + i*128;                                                \
        int p = idx & 15, op = idx >> 4;                                      \
        size_t r0 = (size_t)((k0) + 2*p)*O2 + ((o0 + 2*op) >> 1);             \
        ah0[i] = WhU[r0]; ah1[i] = WhU[r0 + O2];                              \
        al0[i] = WlU[r0]; al1[i] = WlU[r0 + O2];                              \
    }                                                                         \
} while(0)

#define A_WT_STORE(bu) do {                                                   \
    _Pragma("unroll")                                                         \
    for (int i = 0; i < AW; i++) {                                            \
        int idx = tid + i*128;                                                \
        int p = idx & 15, op = idx >> 4, o = 2*op;                            \
        sAh[bu][o][p]   = prmt(ah0[i], ah1[i], 0x5410);                       \
        sAh[bu][o+1][p] = prmt(ah0[i], ah1[i], 0x7632);                       \
        sAl[bu][o][p]   = prmt(al0[i], al1[i], 0x5410);                       \
        sAl[bu][o+1][p] = prmt(al0[i], al1[i], 0x7632);                       \
    }                                                                         \
} while(0)

    /* prologue: tile 0 */
    if (WT == 0) {
        A_CPASYNC(0, 0);
    } else {
        A_WT_LOAD(0);
    }
    #pragma unroll
    for (int i = 0; i < 16; i++) {
        int c = cb + i;
        const float* xp = (c < csplit) ? Xaz + (size_t)c*N
                                       : Xbz + (size_t)(c-csplit)*N;
        bpre[i] = xp[j0 + bn];
    }
    if (WT == 1) A_WT_STORE(0);
    B_FLUSH(0);
    if (WT == 0) asm volatile("cp.async.wait_group 0;");
    __syncthreads();

    const int ntiles = C >> 5;
    for (int kt = 0; kt < ntiles; kt++) {
        const int cur = kt & 1, nxt = cur ^ 1;
        const bool more = (kt + 1 < ntiles);
        if (more) {
            int k0 = (kt + 1) << 5;
            if (WT == 0) {
                A_CPASYNC(nxt, k0 >> 1);
            } else {
                A_WT_LOAD(k0);
            }
            #pragma unroll
            for (int i = 0; i < 16; i++) {
                int cg = k0 + cb + i;
                const float* xp = (cg < csplit) ? Xaz + (size_t)cg*N
                                                : Xbz + (size_t)(cg-csplit)*N;
                bpre[i] = xp[j0 + bn];
            }
        }
        /* compute from current buffer */
        #pragma unroll
        for (int s = 0; s < 2; s++) {
            int s8 = s*8;
            unsigned ah[MT][4], al[MT][4], bh[4][2], bl[4][2];
            #pragma unroll
            for (int mt = 0; mt < MT; mt++) {
                int r0 = wm*(BM/2) + mt*16 + g;
                ah[mt][0]=sAh[cur][r0][s8+t];    al[mt][0]=sAl[cur][r0][s8+t];
                ah[mt][1]=sAh[cur][r0+8][s8+t];  al[mt][1]=sAl[cur][r0+8][s8+t];
                ah[mt][2]=sAh[cur][r0][s8+t+4];  al[mt][2]=sAl[cur][r0][s8+t+4];
                ah[mt][3]=sAh[cur][r0+8][s8+t+4];al[mt][3]=sAl[cur][r0+8][s8+t+4];
            }
            #pragma unroll
            for (int nt = 0; nt < 4; nt++) {
                int cc = wn*32 + nt*8 + g;
                bh[nt][0]=sBh[cur][s8+t][cc];   bl[nt][0]=sBl[cur][s8+t][cc];
                bh[nt][1]=sBh[cur][s8+t+4][cc]; bl[nt][1]=sBl[cur][s8+t+4][cc];
            }
            #pragma unroll
            for (int mt = 0; mt < MT; mt++)
                #pragma unroll
                for (int nt = 0; nt < 4; nt++) {
                    mma16(acc[mt][nt], ah[mt], bh[nt]);
                    mma16(acc[mt][nt], ah[mt], bl[nt]);
                    mma16(acc[mt][nt], al[mt], bh[nt]);
                }
        }
        if (more) {
            if (WT == 1) A_WT_STORE(nxt);
            B_FLUSH(nxt);
        }
        if (WT == 0) asm volatile("cp.async.wait_group 0;");
        __syncthreads();
    }
    /* epilogue */
    #pragma unroll
    for (int mt = 0; mt < MT; mt++) {
        #pragma unroll
        for (int nt = 0; nt < 4; nt++) {
            int row0 = o0 + wm*(BM/2) + mt*16 + g;
            int col0 = j0 + wn*32 + nt*8 + 2*t;
            #pragma unroll
            for (int e = 0; e < 4; e++) {
                int o  = row0 + (e >> 1)*8;
                int jj = col0 + (e & 1);
                float v = acc[mt][nt][e]*alpha + (bias ? bias[o] : 0.f);
                if (act == 2) v = v > 0.f ? v : (__expf(v) - 1.f);
                size_t off = (size_t)z*(size_t)outz + (size_t)o*N + jj;
                if (res) v += res[(size_t)z*(size_t)resz + (size_t)o*N + jj];
                Out[off] = v;
            }
        }
    }
#undef B_FLUSH
#undef A_CPASYNC
#undef A_WT_LOAD
#undef A_WT_STORE
}

/* linear attention stage 1: z in 0..3 pseudo-batch (stream x batch) */
__global__ void __launch_bounds__(256) attn_kv_kernel(
    const float* __restrict__ K, long long kz,
    const float* __restrict__ V, long long vz,
    float* __restrict__ part, int ns)
{
    int chunk = blockIdx.x, h = blockIdx.y, z = blockIdx.z;
    int mlen = ns / NCHUNK, m0 = chunk * mlen;
    const float* Kb = K + (size_t)z*(size_t)kz;
    const float* Vb = V + (size_t)z*(size_t)vz;
    __shared__ float ks[64][33];
    __shared__ float vs[64][33];
    int tid = threadIdx.x;
    int qi0 = (tid>>4)*4, ki0 = (tid&15)*4;
    float acc[4][4]={{0,0,0,0},{0,0,0,0},{0,0,0,0},{0,0,0,0}};
    float ksum = 0.f, invm = 1.f/(float)ns;
    for (int mt = 0; mt < mlen; mt += 32) {
        __syncthreads();
        for (int idx = tid; idx < 64*32; idx += 256) {
            int d = idx>>5, mm = idx&31, m = m0+mt+mm;
            float kr = Kb[(size_t)(d*4+h)*ns + m];
            ks[d][mm] = kr>0.f ? kr+1.f : __expf(kr);
            vs[d][mm] = Vb[(size_t)(d*4+h)*ns + m]*invm;
        }
        __syncthreads();
        if (tid < 64) {
            #pragma unroll
            for (int mm=0;mm<32;mm++) ksum += ks[tid][mm];
        }
        #pragma unroll 4
        for (int mm=0;mm<32;mm++){
            float vv[4], kv[4];
            #pragma unroll
            for (int i=0;i<4;i++) vv[i]=vs[qi0+i][mm];
            #pragma unroll
            for (int j=0;j<4;j++) kv[j]=ks[ki0+j][mm];
            #pragma unroll
            for (int i=0;i<4;i++)
                #pragma unroll
                for (int j=0;j<4;j++) acc[i][j]+=vv[i]*kv[j];
        }
    }
    float* dst = part + (size_t)chunk*KVSLOT;
    size_t base = (size_t)(z*4+h)*64;
    #pragma unroll
    for (int i=0;i<4;i++)
        #pragma unroll
        for (int j=0;j<4;j++)
            dst[(base+qi0+i)*64 + ki0+j] = acc[i][j];
    if (tid < 64) dst[65536 + base + tid] = ksum;
}

__global__ void kv_reduce_kernel(const float* __restrict__ part, float* __restrict__ o)
{
    int i = blockIdx.x*256 + threadIdx.x;
    if (i < KVSLOT) {
        float s = 0.f;
        #pragma unroll
        for (int c=0;c<NCHUNK;c++) s += part[(size_t)c*KVSLOT + i];
        o[i] = s;
    }
}

__global__ void __launch_bounds__(128) attn_out_kernel(
    const float* __restrict__ Q, long long qz, const float* __restrict__ KVr,
    float* __restrict__ O_, long long oz, int nq, int ns)
{
    int z = blockIdx.z, h = blockIdx.y;
    int m = blockIdx.x*128 + threadIdx.x;
    __shared__ float kvs[64][64];
    __shared__ float kss[64];
    const float* src = KVr + (size_t)(z*4+h)*4096;
    for (int i = threadIdx.x; i < 4096; i += 128) kvs[i>>6][i&63] = src[i];
    if (threadIdx.x < 64) kss[threadIdx.x] = KVr[65536 + (size_t)(z*4+h)*64 + threadIdx.x];
    __syncthreads();
    const float* Qb = Q + (size_t)z*(size_t)qz;
    float qv[64], denom = 0.f;
    #pragma unroll
    for (int d=0;d<64;d++){
        float q = Qb[(size_t)(d*4+h)*nq + m];
        q = q>0.f ? q+1.f : __expf(q);
        qv[d]=q; denom += q*kss[d];
    }
    float zf = (float)ns/(denom + 1e-6f);
    float* Ob = O_ + (size_t)z*(size_t)oz;
    for (int qd=0; qd<64; qd++){
        float accv = 0.f;
        #pragma unroll
        for (int d=0;d<64;d++) accv += qv[d]*kvs[qd][d];
        Ob[(size_t)(qd*4+h)*nq + m] = accv*zf;
    }
}

__global__ void __launch_bounds__(256) instnorm_relu_kernel(float* X, int C, int n)
{
    int c = blockIdx.x, b = blockIdx.y;
    float* row = X + ((size_t)b*C + c)*n;
    int tid = threadIdx.x;
    float s=0.f, s2=0.f;
    for (int i=tid;i<n;i+=256){ float v=row[i]; s+=v; s2+=v*v; }
    __shared__ float sm1[256], sm2[256];
    sm1[tid]=s; sm2[tid]=s2; __syncthreads();
    for (int st=128;st;st>>=1){
        if (tid<st){ sm1[tid]+=sm1[tid+st]; sm2[tid]+=sm2[tid+st]; }
        __syncthreads();
    }
    float mean = sm1[0]/(float)n;
    float var = sm2[0]/(float)n - mean*mean;
    float rstd = rsqrtf(var + 1e-5f);
    for (int i=tid;i<n;i+=256){
        float v = (row[i]-mean)*rstd;
        row[i] = v>0.f ? v : 0.f;
    }
}

__global__ void gat_vec_kernel(const float* __restrict__ gatW,
                               const float* __restrict__ gata, float* __restrict__ wa)
{
    int gg = blockIdx.x, d = threadIdx.x;
    const float* W = gatW + (size_t)gg*DD*DD;
    const float* a = gata + (size_t)gg*2*DD;
    float s1=0.f, s2=0.f;
    for (int o=0;o<DD;o++){ float w=W[(size_t)d*DD+o]; s1+=w*a[o]; s2+=w*a[DD+o]; }
    wa[gg*2*DD + d] = s1;
    wa[gg*2*DD + DD + d] = s2;
}

__global__ void __launch_bounds__(256) gat_agg_kernel(
    const float* __restrict__ d3, const float* __restrict__ d2d,
    const float* __restrict__ wa, float* __restrict__ agg, int n)
{
    int b = blockIdx.y;
    int warp = threadIdx.x>>5, lane = threadIdx.x&31;
    int nn = blockIdx.x*8 + warp;
    const float* Wa1 = wa;
    const float* Wa2 = wa + DD;
    const float* d3b = d3 + (size_t)b*DD*n;
    const float* d2b = d2d + (size_t)b*DD*(size_t)n*8;
    size_t n8 = (size_t)n*8;
    float x3[8], w2v[8];
    float sself=0.f, s0=0.f;
    #pragma unroll
    for (int r=0;r<8;r++){
        int d = lane + r*32;
        x3[r]=d3b[(size_t)d*n+nn]; w2v[r]=Wa2[d];
        sself += x3[r]*Wa1[d]; s0 += x3[r]*w2v[r];
    }
    #pragma unroll
    for (int off=16;off;off>>=1){
        sself += __shfl_xor_sync(0xffffffffu, sself, off);
        s0    += __shfl_xor_sync(0xffffffffu, s0, off);
    }
    float e[9]; e[0] = sself + s0;
    size_t nbase = (size_t)nn*8;
    #pragma unroll
    for (int l=1;l<9;l++){
        float sl = 0.f;
        #pragma unroll
        for (int r=0;r<8;r++)
            sl += d2b[(size_t)(lane+r*32)*n8 + nbase + (l-1)] * w2v[r];
        #pragma unroll
        for (int off=16;off;off>>=1) sl += __shfl_xor_sync(0xffffffffu, sl, off);
        e[l] = sself + sl;
    }
    float mx = -1e30f;
    #pragma unroll
    for (int l=0;l<9;l++){ e[l] = e[l]>0.f ? e[l] : 0.2f*e[l]; mx = fmaxf(mx, e[l]); }
    float sum = 0.f;
    #pragma unroll
    for (int l=0;l<9;l++){ e[l] = __expf(e[l]-mx); sum += e[l]; }
    float inv = 1.f/sum;
    float accv[8];
    #pragma unroll
    for (int r=0;r<8;r++) accv[r] = e[0]*inv*x3[r];
    #pragma unroll
    for (int l=1;l<9;l++){
        float al = e[l]*inv;
        #pragma unroll
        for (int r=0;r<8;r++)
            accv[r] += al * d2b[(size_t)(lane+r*32)*n8 + nbase + (l-1)];
    }
    float* ab = agg + (size_t)b*DD*n;
    #pragma unroll
    for (int r=0;r<8;r++) ab[(size_t)(lane+r*32)*n + nn] = accv[r];
}

__global__ void colnorm_kernel(float* X, unsigned short* H, unsigned short* L, int n)
{
    int b = blockIdx.y;
    int col = blockIdx.x*256 + threadIdx.x;
    size_t zb = (size_t)b*DD*n;
    float* Xb = X + zb;
    float s = 0.f;
    for (int d=0;d<DD;d++){ float v=Xb[(size_t)d*n+col]; s += v*v; }
    float inv = 1.f / fmaxf(sqrtf(s), 1e-12f);
    for (int d=0;d<DD;d++){
        float v = Xb[(size_t)d*n+col]*inv;
        Xb[(size_t)d*n+col] = v;
        unsigned short hb = bf1(v);
        H[zb + (size_t)d*n + col] = hb;
        L[zb + (size_t)d*n + col] = bf1(v - bf2f(hb));
    }
}

__global__ void __launch_bounds__(256) row_stats_kernel(
    const float* __restrict__ S, float* rmax, float* rsum, int n1, int n2)
{
    int br = blockIdx.y*n1 + blockIdx.x;
    const float* row = S + (size_t)br*n2;
    int tid = threadIdx.x;
    __shared__ float sm[256];
    float mx = -1e30f;
    for (int j=tid;j<n2;j+=256) mx = fmaxf(mx, row[j]);
    sm[tid]=mx; __syncthreads();
    for (int st=128;st;st>>=1){ if (tid<st) sm[tid]=fmaxf(sm[tid],sm[tid+st]); __syncthreads(); }
    mx = sm[0]; __syncthreads();
    float s = 0.f;
    for (int j=tid;j<n2;j+=256) s += __expf(row[j]-mx);
    sm[tid]=s; __syncthreads();
    for (int st=128;st;st>>=1){ if (tid<st) sm[tid]+=sm[tid+st]; __syncthreads(); }
    if (tid==0){ rmax[br]=mx; rsum[br]=sm[0]; }
}

__global__ void col_stats_kernel(const float* __restrict__ S,
                                 float* cmax, float* csum, int n1, int n2)
{
    int b = blockIdx.y;
    int c = blockIdx.x*256 + threadIdx.x;
    const float* Sb = S + (size_t)b*n1*n2;
    float mx = -1e30f, s = 0.f;
    for (int r=0;r<n1;r++){
        float v = Sb[(size_t)r*n2 + c];
        if (v > mx){ s = s*__expf(mx-v) + 1.f; mx = v; }
        else s += __expf(v-mx);
    }
    cmax[b*n1 + c] = mx;
    csum[b*n1 + c] = s;
}

__global__ void conf_kernel(const float* __restrict__ S,
    const float* __restrict__ rmax, const float* __restrict__ rsum,
    const float* __restrict__ cmax, const float* __restrict__ csum,
    float* __restrict__ conf)
{
    size_t idx = (size_t)blockIdx.x*256 + threadIdx.x;
    int z = (int)(idx / ((size_t)NB*NB));
    size_t rem = idx - (size_t)z*NB*NB;
    int n = (int)(rem / NB), m = (int)(rem % NB);
    float s = S[idx];
    conf[idx] = __expf(2.f*s - rmax[z*NB+n] - cmax[z*NB+m])
                / (rsum[z*NB+n]*csum[z*NB+m]);
}

__global__ void __launch_bounds__(256) rowargmax_kernel(
    const float* __restrict__ conf0, int* i0, float* m0)
{
    int n = blockIdx.x;
    const float* row = conf0 + (size_t)n*NB;
    int tid = threadIdx.x;
    float best = -1e30f; int bidx = 0;
    for (int m=tid;m<NB;m+=256){ float v=row[m]; if (v>best){best=v;bidx=m;} }
    __shared__ float bv[256]; __shared__ int bi[256];
    bv[tid]=best; bi[tid]=bidx; __syncthreads();
    for (int st=128;st;st>>=1){
        if (tid<st){
            if (bv[tid+st]>bv[tid] || (bv[tid+st]==bv[tid] && bi[tid+st]<bi[tid])){
                bv[tid]=bv[tid+st]; bi[tid]=bi[tid+st];
            }
        }
        __syncthreads();
    }
    if (tid==0){ i0[n]=bi[0]; m0[n]=bv[0]; }
}

__global__ void colargmax_kernel(const float* __restrict__ conf0, int* i1, float* m1)
{
    int m = blockIdx.x*256 + threadIdx.x;
    float best = -1e30f; int bidx = 0;
    for (int n=0;n<NB;n++){
        float v = conf0[(size_t)n*NB + m];
        if (v > best){ best=v; bidx=n; }
    }
    i1[m]=bidx; m1[m]=best;
}

__global__ void match0_kernel(const int* i0, const int* i1, const float* m0,
                              float* out, float* ms0buf, int* valid0)
{
    int n = blockIdx.x*256 + threadIdx.x;
    int t = i0[n];
    int mutual = (i1[t] == n);
    float ms0 = mutual ? m0[n] : 0.f;
    int v0 = mutual && (ms0 > 0.2f);
    out[n] = v0 ? (float)t : -1.f;
    out[2*NB + n] = ms0;
    ms0buf[n] = ms0;
    valid0[n] = v0;
}

__global__ void match1_kernel(const int* i0, const int* i1,
                              const float* ms0buf, const int* valid0, float* out)
{
    int m = blockIdx.x*256 + threadIdx.x;
    int t = i1[m];
    int mutual = (i0[t] == m);
    float ms1 = mutual ? ms0buf[t] : 0.f;
    int v1 = mutual && valid0[t];
    out[NB + m] = v1 ? (float)t : -1.f;
    out[3*NB + m] = ms1;
}

/* --------------------------------- host ---------------------------------- */
static void* gsym(const void* s){ void* p=nullptr; cudaGetSymbolAddress(&p, s); return p; }
typedef unsigned short u16;

extern "C" void kernel_launch(void* const* d_in, const int* in_sizes, int n_in,
                              void* d_out, int out_size)
{
    const float* in_dq   = (const float*)d_in[0];
    const float* in_d3   = (const float*)d_in[1];
    const float* in_d2db = (const float*)d_in[2];
    const float* projb   = (const float*)d_in[4];
    const float* mergeb  = (const float*)d_in[6];
    const float* mlp1b   = (const float*)d_in[8];
    const float* mlp2b   = (const float*)d_in[10];
    const float* gatW    = (const float*)d_in[11];
    const float* gata    = (const float*)d_in[12];
    const float* finb    = (const float*)d_in[14];
    float* out = (float*)d_out;

    float* act    = (float*)gsym(g_act);
    float* qkv    = (float*)gsym(g_qkv);
    float* ob     = (float*)gsym(g_ob);
    float* msg    = (float*)gsym(g_msg);
    float* tb     = (float*)gsym(g_tb);
    float* agg    = (float*)gsym(g_agg);
    float* fb     = (float*)gsym(g_fb);
    u16*   fbh    = (u16*)gsym(g_fbh);
    u16*   fbl    = (u16*)gsym(g_fbl);
    float* sc     = (float*)gsym(g_sc);
    float* kvpart = (float*)gsym(g_kvpart);
    float* kvred  = (float*)gsym(g_kvred);
    float* wa     = (float*)gsym(g_wa);
    float* rmax   = (float*)gsym(g_rmax);
    float* rsum   = (float*)gsym(g_rsum);
    float* cmax   = (float*)gsym(g_cmax);
    float* csum   = (float*)gsym(g_csum);
    int*   i0     = (int*)gsym(g_i0);
    int*   i1     = (int*)gsym(g_i1);
    int*   valid0 = (int*)gsym(g_valid0);
    float* m0     = (float*)gsym(g_m0);
    float* m1     = (float*)gsym(g_m1);
    float* ms0buf = (float*)gsym(g_ms0buf);
    u16*   wbh    = (u16*)gsym(g_wbh);
    u16*   wbl    = (u16*)gsym(g_wbl);

    const int N = NB;
    const long long DN  = (long long)DD*N;
    const long long QKN = (long long)3*DD*N;
    const long long TBN = (long long)2*DD*N;
    float* dqp = act;
    float* d3p = act + 2*DN;
    float* dqo = act + 4*DN;

    cvt_all<<<(WTOT/4+255)/256,256>>>((const float*)d_in[3], (const float*)d_in[5],
                                      (const float*)d_in[7], (const float*)d_in[9],
                                      gatW, (const float*)d_in[13], wbh, wbl);

    cudaMemcpyAsync(dqp, in_dq, (size_t)2*DN*sizeof(float), cudaMemcpyDeviceToDevice);
    cudaMemcpyAsync(d3p, in_d3, (size_t)2*DN*sizeof(float), cudaMemcpyDeviceToDevice);
    gat_vec_kernel<<<4,256>>>(gatW, gata, wa);

    int gi = 0, ai = 0;
    for (int step = 0; step < 12; step++) {
        int t = step % 3;
        if (t == 0) {
            gat_agg_kernel<<<dim3(N/8,2),256>>>(d3p, in_d2db, wa + gi*2*DD, agg, N);
            gemm_tc<64,1><<<dim3(N/64,4,2),128>>>(wbh+OFF_GAT+(size_t)gi*DD*DD,
                wbl+OFF_GAT+(size_t)gi*DD*DD, 0, DD,
                agg, DN, agg, DN, DD, nullptr, nullptr,0,
                d3p, DN, DD, N, 1.f, 2);
            gi++;
        } else {
            const u16* pwh = wbh + OFF_PROJ + (size_t)ai*3*DD*DD;
            const u16* pwl = wbl + OFF_PROJ + (size_t)ai*3*DD*DD;
            const float* pb = projb + (size_t)ai*3*DD;
            if (t == 1) {
                gemm_tc<128,0><<<dim3(N/64,6,4),128>>>(pwh, pwl, 0, 768,
                    act, DN, act, DN, DD, pb, nullptr,0, qkv, QKN, DD, N, 1.f, 0);
            } else {
                cudaMemcpyAsync(dqo, dqp, (size_t)2*DN*sizeof(float),
                                cudaMemcpyDeviceToDevice);
                gemm_tc<128,0><<<dim3(N/64,2,4),128>>>(pwh, pwl, 0, DD,
                    act, DN, act, DN, DD, pb, nullptr,0, qkv, QKN, DD, N, 1.f, 0);
                gemm_tc<128,0><<<dim3(N/64,4,4),128>>>(pwh+DD*DD, pwl+DD*DD, 0, 512,
                    d3p, DN, d3p, DN, DD, pb+DD, nullptr,0,
                    qkv + (size_t)DD*N, QKN, DD, N, 1.f, 0);
            }
            attn_kv_kernel<<<dim3(NCHUNK,4,4),256>>>(qkv + (size_t)DD*N, QKN,
                                                     qkv + (size_t)2*DD*N, QKN,
                                                     kvpart, N);
            kv_reduce_kernel<<<(KVSLOT+255)/256,256>>>(kvpart, kvred);
            attn_out_kernel<<<dim3(N/128,4,4),128>>>(qkv, QKN, kvred, ob, DN, N, N);
            gemm_tc<128,0><<<dim3(N/64,2,4),128>>>(wbh+OFF_MERGE+(size_t)ai*DD*DD,
                wbl+OFF_MERGE+(size_t)ai*DD*DD, 0, DD,
                ob, DN, ob, DN, DD, mergeb+(size_t)ai*DD, nullptr,0,
                msg, DN, DD, N, 1.f, 0);
            gemm_tc<128,0><<<dim3(N/64,4,4),128>>>(wbh+OFF_MLP1+(size_t)ai*512*512,
                wbl+OFF_MLP1+(size_t)ai*512*512, 0, 512,
                act, DN, msg, DN, DD, mlp1b+(size_t)ai*512, nullptr,0,
                tb, TBN, 512, N, 1.f, 0);
            instnorm_relu_kernel<<<dim3(512,4),256>>>(tb, 512, N);
            gemm_tc<128,0><<<dim3(N/64,2,4),128>>>(wbh+OFF_MLP2+(size_t)ai*DD*512,
                wbl+OFF_MLP2+(size_t)ai*DD*512, 0, DD,
                tb, TBN, tb, TBN, 512, mlp2b+(size_t)ai*DD, act, DN,
                act, DN, 512, N, 1.f, 0);
            ai++;
        }
    }

    gemm_tc<128,0><<<dim3(N/64,2,4),128>>>(wbh+OFF_FIN, wbl+OFF_FIN, 0, DD,
        act, DN, act, DN, DD, finb, nullptr,0, fb, DN, DD, N, 1.f, 0);
    colnorm_kernel<<<dim3(N/256,4),256>>>(fb, fbh, fbl, N);

    gemm_tc<128,1><<<dim3(N/64,N/128,2),128>>>(fbh, fbl, DN, N,
        fb + 2*DN, DN, fb + 2*DN, DN, DD,
        nullptr, nullptr,0, sc, (long long)N*N, DD, N, 10.f, 0);
    row_stats_kernel<<<dim3(N,2),256>>>(sc, rmax, rsum, N, N);
    col_stats_kernel<<<dim3(N/256,2),256>>>(sc, cmax, csum, N, N);

    float* conf = out + 4*NB;
    conf_kernel<<<(unsigned)((size_t)2*N*N/256),256>>>(sc, rmax, rsum, cmax, csum, conf);
    rowargmax_kernel<<<N,256>>>(conf, i0, m0);
    colargmax_kernel<<<N/256,256>>>(conf, i1, m1);
    match0_kernel<<<N/256,256>>>(i0, i1, m0, out, ms0buf, valid0);
    match1_kernel<<<N/256,256>>>(i0, i1, ms0buf, valid0, out);
}

// round 15
// speedup vs baseline: 1.2017x; 1.0278x over previous
#include <cuda_runtime.h>
#include <cuda_bf16.h>
#include <math.h>

#define DD 256
#define NB 3072
#define NCHUNK 8
#define KVSLOT 66560   /* 4*4*64*64 + 4*4*64 */

#define OFF_PROJ  0
#define SZ_PROJ   (8*3*DD*DD)
#define OFF_MERGE (OFF_PROJ + SZ_PROJ)
#define SZ_MERGE  (8*DD*DD)
#define OFF_MLP1  (OFF_MERGE + SZ_MERGE)
#define SZ_MLP1   (8*2*DD*2*DD)
#define OFF_MLP2  (OFF_MLP1 + SZ_MLP1)
#define SZ_MLP2   (8*DD*2*DD)
#define OFF_GAT   (OFF_MLP2 + SZ_MLP2)
#define SZ_GAT    (4*DD*DD)
#define OFF_FIN   (OFF_GAT + SZ_GAT)
#define SZ_FIN    (DD*DD)
#define WTOT      (OFF_FIN + SZ_FIN)

__device__ float g_act[6*DD*NB];
__device__ float g_qkv[(size_t)4*3*DD*NB];
__device__ float g_ob[4*DD*NB];
__device__ float g_msg[4*DD*NB];
__device__ float g_tb[(size_t)4*2*DD*NB];
__device__ float g_agg[2*DD*NB];
__device__ float g_fb[4*DD*NB];
__device__ unsigned short g_fbh[4*DD*NB], g_fbl[4*DD*NB];
__device__ float g_sc[(size_t)2*NB*NB];
__device__ float g_kvpart[NCHUNK*KVSLOT];
__device__ float g_kvred[KVSLOT];
__device__ float g_wa[4*2*DD];
__device__ float g_rmax[2*NB];
__device__ float g_rsum[2*NB];
__device__ float g_cmax[2*NB];
__device__ float g_csum[2*NB];
__device__ int   g_i0[NB];
__device__ int   g_i1[NB];
__device__ int   g_valid0[NB];
__device__ float g_m0[NB];
__device__ float g_m1[NB];
__device__ float g_ms0buf[NB];
__device__ unsigned short g_wbh[WTOT], g_wbl[WTOT];

__device__ __forceinline__ unsigned packbf(float lo, float hi){
    unsigned r; asm("cvt.rn.bf16x2.f32 %0,%1,%2;":"=r"(r):"f"(hi),"f"(lo)); return r;
}
__device__ __forceinline__ unsigned short bf1(float v){
    __nv_bfloat16 b = __float2bfloat16(v);
    return *reinterpret_cast<unsigned short*>(&b);
}
__device__ __forceinline__ float bf2f(unsigned short u){
    return __uint_as_float(((unsigned)u) << 16);
}
__device__ __forceinline__ unsigned prmt(unsigned a, unsigned b, unsigned s){
    unsigned r; asm("prmt.b32 %0,%1,%2,%3;":"=r"(r):"r"(a),"r"(b),"r"(s)); return r;
}
__device__ __forceinline__ void mma16(float* c, const unsigned* a, const unsigned* b){
    asm volatile("mma.sync.aligned.m16n8k16.row.col.f32.bf16.bf16.f32 "
        "{%0,%1,%2,%3}, {%4,%5,%6,%7}, {%8,%9}, {%0,%1,%2,%3};"
        : "+f"(c[0]),"+f"(c[1]),"+f"(c[2]),"+f"(c[3])
        : "r"(a[0]),"r"(a[1]),"r"(a[2]),"r"(a[3]), "r"(b[0]),"r"(b[1]));
}
__device__ __forceinline__ void cpa16(unsigned dst, const void* src){
    asm volatile("cp.async.ca.shared.global [%0], [%1], 16;"
                 :: "r"(dst), "l"(src));
}
__device__ __forceinline__ unsigned s2u(const void* p){
    return (unsigned)__cvta_generic_to_shared(p);
}
__device__ __forceinline__ void ldm4(unsigned* r, unsigned addr){
    asm volatile("ldmatrix.sync.aligned.m8n8.x4.shared.b16 {%0,%1,%2,%3}, [%4];"
        : "=r"(r[0]),"=r"(r[1]),"=r"(r[2]),"=r"(r[3]) : "r"(addr));
}

__global__ void cvt_all(const float* __restrict__ projw, const float* __restrict__ mergew,
                        const float* __restrict__ mlp1w, const float* __restrict__ mlp2w,
                        const float* __restrict__ gatW,  const float* __restrict__ finw,
                        unsigned short* __restrict__ H, unsigned short* __restrict__ L)
{
    int i = blockIdx.x*256 + threadIdx.x;
    if (i >= WTOT/4) return;
    int e = i*4;
    const float* src;
    if      (e < OFF_MERGE) src = projw  + (e - OFF_PROJ);
    else if (e < OFF_MLP1)  src = mergew + (e - OFF_MERGE);
    else if (e < OFF_MLP2)  src = mlp1w  + (e - OFF_MLP1);
    else if (e < OFF_GAT)   src = mlp2w  + (e - OFF_MLP2);
    else if (e < OFF_FIN)   src = gatW   + (e - OFF_GAT);
    else                    src = finw   + (e - OFF_FIN);
    float4 v = *(const float4*)src;
    unsigned h01 = packbf(v.x, v.y), h23 = packbf(v.z, v.w);
    ((uint2*)H)[i] = make_uint2(h01, h23);
    float lx = v.x - __uint_as_float(h01<<16);
    float ly = v.y - __uint_as_float(h01&0xffff0000u);
    float lz = v.z - __uint_as_float(h23<<16);
    float lw = v.w - __uint_as_float(h23&0xffff0000u);
    ((uint2*)L)[i] = make_uint2(packbf(lx,ly), packbf(lz,lw));
}

/* BF16x3 GEMM. BM templated (64/128); WT templated (0: A via cp.async,
   1: A transposed via register+prmt). A fragments via ldmatrix.x4.
   BN=64, BK=32, 128 threads (2x2 warps), warp tile (BM/2)x32. */
template<int BM, int WT>
__global__ void __launch_bounds__(128) gemm_tc(
    const unsigned short* __restrict__ Wh, const unsigned short* __restrict__ Wl,
    long long wz, int O,
    const float* __restrict__ Xa, long long xaz,
    const float* __restrict__ Xb, long long xbz, int csplit,
    const float* __restrict__ bias,
    const float* __restrict__ res, long long resz,
    float* __restrict__ Out, long long outz,
    int C, int N, float alpha, int act)
{
    constexpr int MT = BM/32;
    constexpr int AW = BM/16;
    __shared__ unsigned sAh[2][BM][20], sAl[2][BM][20];
    __shared__ unsigned sBh[2][16][72], sBl[2][16][72];
    const int z  = blockIdx.z;
    const int o0 = blockIdx.y * BM, j0 = blockIdx.x * 64;
    const unsigned* WhU = (const unsigned*)(Wh + (size_t)z*(size_t)wz);
    const unsigned* WlU = (const unsigned*)(Wl + (size_t)z*(size_t)wz);
    const float* Xaz = Xa + (size_t)z*(size_t)xaz;
    const float* Xbz = Xb + (size_t)z*(size_t)xbz;
    const int tid  = threadIdx.x;
    const int lane = tid & 31, w = tid >> 5;
    const int wm = w >> 1, wn = w & 1;
    const int g = lane >> 2, t = lane & 3;
    const int C2 = C >> 1, O2 = O >> 1;
    const int bn = tid & 63, cb = (tid >> 6) * 16;
    const int lr = lane & 15, lc4 = (lane >> 4) << 2;   /* ldmatrix row/col */

    float acc[MT][4][4];
    #pragma unroll
    for (int i=0;i<MT;i++)
        #pragma unroll
        for (int j=0;j<4;j++)
            #pragma unroll
            for (int k=0;k<4;k++) acc[i][j][k]=0.f;

    unsigned ah0[WT ? AW : 1], al0[WT ? AW : 1];
    unsigned ah1[WT ? AW : 1], al1[WT ? AW : 1];
    float bpre[16];

#define B_FLUSH(bu) do {                                                      \
    _Pragma("unroll")                                                         \
    for (int jj2 = 0; jj2 < 8; jj2++) {                                       \
        float v0 = bpre[2*jj2], v1 = bpre[2*jj2+1];                           \
        unsigned hw = packbf(v0, v1);                                         \
        float h0 = __uint_as_float(hw << 16);                                 \
        float h1 = __uint_as_float(hw & 0xffff0000u);                         \
        unsigned lw = packbf(v0 - h0, v1 - h1);                               \
        int p = (cb >> 1) + jj2;                                              \
        sBh[bu][p][bn] = hw;                                                  \
        sBl[bu][p][bn] = lw;                                                  \
    }                                                                         \
} while(0)

#define A_CPASYNC(bu, kw) do {                                                \
    _Pragma("unroll")                                                         \
    for (int i = 0; i < BM/32; i++) {                                         \
        int idx = tid + i*128;                                                \
        int o = idx >> 2, p4 = (idx & 3) * 4;                                 \
        cpa16(s2u(&sAh[bu][o][p4]), WhU + (size_t)(o0+o)*C2 + (kw) + p4);     \
        cpa16(s2u(&sAl[bu][o][p4]), WlU + (size_t)(o0+o)*C2 + (kw) + p4);     \
    }                                                                         \
    asm volatile("cp.async.commit_group;");                                   \
} while(0)

#define A_WT_LOAD(k0) do {                                                    \
    _Pragma("unroll")                                                         \
    for (int i = 0; i < AW; i++) {                                            \
        int idx = tid + i*128;                                                \
        int p = idx & 15, op = idx >> 4;                                      \
        size_t r0 = (size_t)((k0) + 2*p)*O2 + ((o0 + 2*op) >> 1);             \
        ah0[i] = WhU[r0]; ah1[i] = WhU[r0 + O2];                              \
        al0[i] = WlU[r0]; al1[i] = WlU[r0 + O2];                              \
    }                                                                         \
} while(0)

#define A_WT_STORE(bu) do {                                                   \
    _Pragma("unroll")                                                         \
    for (int i = 0; i < AW; i++) {                                            \
        int idx = tid + i*128;                                                \
        int p = idx & 15, op = idx >> 4, o = 2*op;                            \
        sAh[bu][o][p]   = prmt(ah0[i], ah1[i], 0x5410);                       \
        sAh[bu][o+1][p] = prmt(ah0[i], ah1[i], 0x7632);                       \
        sAl[bu][o][p]   = prmt(al0[i], al1[i], 0x5410);                       \
        sAl[bu][o+1][p] = prmt(al0[i], al1[i], 0x7632);                       \
    }                                                                         \
} while(0)

    /* prologue: tile 0 */
    if (WT == 0) {
        A_CPASYNC(0, 0);
    } else {
        A_WT_LOAD(0);
    }
    #pragma unroll
    for (int i = 0; i < 16; i++) {
        int c = cb + i;
        const float* xp = (c < csplit) ? Xaz + (size_t)c*N
                                       : Xbz + (size_t)(c-csplit)*N;
        bpre[i] = xp[j0 + bn];
    }
    if (WT == 1) A_WT_STORE(0);
    B_FLUSH(0);
    if (WT == 0) asm volatile("cp.async.wait_group 0;");
    __syncthreads();

    const int ntiles = C >> 5;
    for (int kt = 0; kt < ntiles; kt++) {
        const int cur = kt & 1, nxt = cur ^ 1;
        const bool more = (kt + 1 < ntiles);
        if (more) {
            int k0 = (kt + 1) << 5;
            if (WT == 0) {
                A_CPASYNC(nxt, k0 >> 1);
            } else {
                A_WT_LOAD(k0);
            }
            #pragma unroll
            for (int i = 0; i < 16; i++) {
                int cg = k0 + cb + i;
                const float* xp = (cg < csplit) ? Xaz + (size_t)cg*N
                                                : Xbz + (size_t)(cg-csplit)*N;
                bpre[i] = xp[j0 + bn];
            }
        }
        /* compute from current buffer */
        #pragma unroll
        for (int s = 0; s < 2; s++) {
            int s8 = s*8;
            unsigned ah[MT][4], al[MT][4], bh[4][2], bl[4][2];
            #pragma unroll
            for (int mt = 0; mt < MT; mt++) {
                int r0 = wm*(BM/2) + mt*16;
                ldm4(ah[mt], s2u(&sAh[cur][r0 + lr][s8 + lc4]));
                ldm4(al[mt], s2u(&sAl[cur][r0 + lr][s8 + lc4]));
            }
            #pragma unroll
            for (int nt = 0; nt < 4; nt++) {
                int cc = wn*32 + nt*8 + g;
                bh[nt][0]=sBh[cur][s8+t][cc];   bl[nt][0]=sBl[cur][s8+t][cc];
                bh[nt][1]=sBh[cur][s8+t+4][cc]; bl[nt][1]=sBl[cur][s8+t+4][cc];
            }
            #pragma unroll
            for (int mt = 0; mt < MT; mt++)
                #pragma unroll
                for (int nt = 0; nt < 4; nt++) {
                    mma16(acc[mt][nt], ah[mt], bh[nt]);
                    mma16(acc[mt][nt], ah[mt], bl[nt]);
                    mma16(acc[mt][nt], al[mt], bh[nt]);
                }
        }
        if (more) {
            if (WT == 1) A_WT_STORE(nxt);
            B_FLUSH(nxt);
        }
        if (WT == 0) asm volatile("cp.async.wait_group 0;");
        __syncthreads();
    }
    /* epilogue */
    #pragma unroll
    for (int mt = 0; mt < MT; mt++) {
        #pragma unroll
        for (int nt = 0; nt < 4; nt++) {
            int row0 = o0 + wm*(BM/2) + mt*16 + g;
            int col0 = j0 + wn*32 + nt*8 + 2*t;
            #pragma unroll
            for (int e = 0; e < 4; e++) {
                int o  = row0 + (e >> 1)*8;
                int jj = col0 + (e & 1);
                float v = acc[mt][nt][e]*alpha + (bias ? bias[o] : 0.f);
                if (act == 2) v = v > 0.f ? v : (__expf(v) - 1.f);
                size_t off = (size_t)z*(size_t)outz + (size_t)o*N + jj;
                if (res) v += res[(size_t)z*(size_t)resz + (size_t)o*N + jj];
                Out[off] = v;
            }
        }
    }
#undef B_FLUSH
#undef A_CPASYNC
#undef A_WT_LOAD
#undef A_WT_STORE
}

/* linear attention stage 1: z in 0..3 pseudo-batch (stream x batch) */
__global__ void __launch_bounds__(256) attn_kv_kernel(
    const float* __restrict__ K, long long kz,
    const float* __restrict__ V, long long vz,
    float* __restrict__ part, int ns)
{
    int chunk = blockIdx.x, h = blockIdx.y, z = blockIdx.z;
    int mlen = ns / NCHUNK, m0 = chunk * mlen;
    const float* Kb = K + (size_t)z*(size_t)kz;
    const float* Vb = V + (size_t)z*(size_t)vz;
    __shared__ float ks[64][33];
    __shared__ float vs[64][33];
    int tid = threadIdx.x;
    int qi0 = (tid>>4)*4, ki0 = (tid&15)*4;
    float acc[4][4]={{0,0,0,0},{0,0,0,0},{0,0,0,0},{0,0,0,0}};
    float ksum = 0.f, invm = 1.f/(float)ns;
    for (int mt = 0; mt < mlen; mt += 32) {
        __syncthreads();
        for (int idx = tid; idx < 64*32; idx += 256) {
            int d = idx>>5, mm = idx&31, m = m0+mt+mm;
            float kr = Kb[(size_t)(d*4+h)*ns + m];
            ks[d][mm] = kr>0.f ? kr+1.f : __expf(kr);
            vs[d][mm] = Vb[(size_t)(d*4+h)*ns + m]*invm;
        }
        __syncthreads();
        if (tid < 64) {
            #pragma unroll
            for (int mm=0;mm<32;mm++) ksum += ks[tid][mm];
        }
        #pragma unroll 4
        for (int mm=0;mm<32;mm++){
            float vv[4], kv[4];
            #pragma unroll
            for (int i=0;i<4;i++) vv[i]=vs[qi0+i][mm];
            #pragma unroll
            for (int j=0;j<4;j++) kv[j]=ks[ki0+j][mm];
            #pragma unroll
            for (int i=0;i<4;i++)
                #pragma unroll
                for (int j=0;j<4;j++) acc[i][j]+=vv[i]*kv[j];
        }
    }
    float* dst = part + (size_t)chunk*KVSLOT;
    size_t base = (size_t)(z*4+h)*64;
    #pragma unroll
    for (int i=0;i<4;i++)
        #pragma unroll
        for (int j=0;j<4;j++)
            dst[(base+qi0+i)*64 + ki0+j] = acc[i][j];
    if (tid < 64) dst[65536 + base + tid] = ksum;
}

__global__ void kv_reduce_kernel(const float* __restrict__ part, float* __restrict__ o)
{
    int i = blockIdx.x*256 + threadIdx.x;
    if (i < KVSLOT) {
        float s = 0.f;
        #pragma unroll
        for (int c=0;c<NCHUNK;c++) s += part[(size_t)c*KVSLOT + i];
        o[i] = s;
    }
}

__global__ void __launch_bounds__(128) attn_out_kernel(
    const float* __restrict__ Q, long long qz, const float* __restrict__ KVr,
    float* __restrict__ O_, long long oz, int nq, int ns)
{
    int z = blockIdx.z, h = blockIdx.y;
    int m = blockIdx.x*128 + threadIdx.x;
    __shared__ float kvs[64][64];
    __shared__ float kss[64];
    const float* src = KVr + (size_t)(z*4+h)*4096;
    for (int i = threadIdx.x; i < 4096; i += 128) kvs[i>>6][i&63] = src[i];
    if (threadIdx.x < 64) kss[threadIdx.x] = KVr[65536 + (size_t)(z*4+h)*64 + threadIdx.x];
    __syncthreads();
    const float* Qb = Q + (size_t)z*(size_t)qz;
    float qv[64], denom = 0.f;
    #pragma unroll
    for (int d=0;d<64;d++){
        float q = Qb[(size_t)(d*4+h)*nq + m];
        q = q>0.f ? q+1.f : __expf(q);
        qv[d]=q; denom += q*kss[d];
    }
    float zf = (float)ns/(denom + 1e-6f);
    float* Ob = O_ + (size_t)z*(size_t)oz;
    for (int qd=0; qd<64; qd++){
        float accv = 0.f;
        #pragma unroll
        for (int d=0;d<64;d++) accv += qv[d]*kvs[qd][d];
        Ob[(size_t)(qd*4+h)*nq + m] = accv*zf;
    }
}

__global__ void __launch_bounds__(256) instnorm_relu_kernel(float* X, int C, int n)
{
    int c = blockIdx.x, b = blockIdx.y;
    float* row = X + ((size_t)b*C + c)*n;
    int tid = threadIdx.x;
    float s=0.f, s2=0.f;
    for (int i=tid;i<n;i+=256){ float v=row[i]; s+=v; s2+=v*v; }
    __shared__ float sm1[256], sm2[256];
    sm1[tid]=s; sm2[tid]=s2; __syncthreads();
    for (int st=128;st;st>>=1){
        if (tid<st){ sm1[tid]+=sm1[tid+st]; sm2[tid]+=sm2[tid+st]; }
        __syncthreads();
    }
    float mean = sm1[0]/(float)n;
    float var = sm2[0]/(float)n - mean*mean;
    float rstd = rsqrtf(var + 1e-5f);
    for (int i=tid;i<n;i+=256){
        float v = (row[i]-mean)*rstd;
        row[i] = v>0.f ? v : 0.f;
    }
}

__global__ void gat_vec_kernel(const float* __restrict__ gatW,
                               const float* __restrict__ gata, float* __restrict__ wa)
{
    int gg = blockIdx.x, d = threadIdx.x;
    const float* W = gatW + (size_t)gg*DD*DD;
    const float* a = gata + (size_t)gg*2*DD;
    float s1=0.f, s2=0.f;
    for (int o=0;o<DD;o++){ float w=W[(size_t)d*DD+o]; s1+=w*a[o]; s2+=w*a[DD+o]; }
    wa[gg*2*DD + d] = s1;
    wa[gg*2*DD + DD + d] = s2;
}

__global__ void __launch_bounds__(256) gat_agg_kernel(
    const float* __restrict__ d3, const float* __restrict__ d2d,
    const float* __restrict__ wa, float* __restrict__ agg, int n)
{
    int b = blockIdx.y;
    int warp = threadIdx.x>>5, lane = threadIdx.x&31;
    int nn = blockIdx.x*8 + warp;
    const float* Wa1 = wa;
    const float* Wa2 = wa + DD;
    const float* d3b = d3 + (size_t)b*DD*n;
    const float* d2b = d2d + (size_t)b*DD*(size_t)n*8;
    size_t n8 = (size_t)n*8;
    float x3[8], w2v[8];
    float sself=0.f, s0=0.f;
    #pragma unroll
    for (int r=0;r<8;r++){
        int d = lane + r*32;
        x3[r]=d3b[(size_t)d*n+nn]; w2v[r]=Wa2[d];
        sself += x3[r]*Wa1[d]; s0 += x3[r]*w2v[r];
    }
    #pragma unroll
    for (int off=16;off;off>>=1){
        sself += __shfl_xor_sync(0xffffffffu, sself, off);
        s0    += __shfl_xor_sync(0xffffffffu, s0, off);
    }
    float e[9]; e[0] = sself + s0;
    size_t nbase = (size_t)nn*8;
    #pragma unroll
    for (int l=1;l<9;l++){
        float sl = 0.f;
        #pragma unroll
        for (int r=0;r<8;r++)
            sl += d2b[(size_t)(lane+r*32)*n8 + nbase + (l-1)] * w2v[r];
        #pragma unroll
        for (int off=16;off;off>>=1) sl += __shfl_xor_sync(0xffffffffu, sl, off);
        e[l] = sself + sl;
    }
    float mx = -1e30f;
    #pragma unroll
    for (int l=0;l<9;l++){ e[l] = e[l]>0.f ? e[l] : 0.2f*e[l]; mx = fmaxf(mx, e[l]); }
    float sum = 0.f;
    #pragma unroll
    for (int l=0;l<9;l++){ e[l] = __expf(e[l]-mx); sum += e[l]; }
    float inv = 1.f/sum;
    float accv[8];
    #pragma unroll
    for (int r=0;r<8;r++) accv[r] = e[0]*inv*x3[r];
    #pragma unroll
    for (int l=1;l<9;l++){
        float al = e[l]*inv;
        #pragma unroll
        for (int r=0;r<8;r++)
            accv[r] += al * d2b[(size_t)(lane+r*32)*n8 + nbase + (l-1)];
    }
    float* ab = agg + (size_t)b*DD*n;
    #pragma unroll
    for (int r=0;r<8;r++) ab[(size_t)(lane+r*32)*n + nn] = accv[r];
}

__global__ void colnorm_kernel(float* X, unsigned short* H, unsigned short* L, int n)
{
    int b = blockIdx.y;
    int col = blockIdx.x*256 + threadIdx.x;
    size_t zb = (size_t)b*DD*n;
    float* Xb = X + zb;
    float s = 0.f;
    for (int d=0;d<DD;d++){ float v=Xb[(size_t)d*n+col]; s += v*v; }
    float inv = 1.f / fmaxf(sqrtf(s), 1e-12f);
    for (int d=0;d<DD;d++){
        float v = Xb[(size_t)d*n+col]*inv;
        Xb[(size_t)d*n+col] = v;
        unsigned short hb = bf1(v);
        H[zb + (size_t)d*n + col] = hb;
        L[zb + (size_t)d*n + col] = bf1(v - bf2f(hb));
    }
}

__global__ void __launch_bounds__(256) row_stats_kernel(
    const float* __restrict__ S, float* rmax, float* rsum, int n1, int n2)
{
    int br = blockIdx.y*n1 + blockIdx.x;
    const float* row = S + (size_t)br*n2;
    int tid = threadIdx.x;
    __shared__ float sm[256];
    float mx = -1e30f;
    for (int j=tid;j<n2;j+=256) mx = fmaxf(mx, row[j]);
    sm[tid]=mx; __syncthreads();
    for (int st=128;st;st>>=1){ if (tid<st) sm[tid]=fmaxf(sm[tid],sm[tid+st]); __syncthreads(); }
    mx = sm[0]; __syncthreads();
    float s = 0.f;
    for (int j=tid;j<n2;j+=256) s += __expf(row[j]-mx);
    sm[tid]=s; __syncthreads();
    for (int st=128;st;st>>=1){ if (tid<st) sm[tid]+=sm[tid+st]; __syncthreads(); }
    if (tid==0){ rmax[br]=mx; rsum[br]=sm[0]; }
}

__global__ void col_stats_kernel(const float* __restrict__ S,
                                 float* cmax, float* csum, int n1, int n2)
{
    int b = blockIdx.y;
    int c = blockIdx.x*256 + threadIdx.x;
    const float* Sb = S + (size_t)b*n1*n2;
    float mx = -1e30f, s = 0.f;
    for (int r=0;r<n1;r++){
        float v = Sb[(size_t)r*n2 + c];
        if (v > mx){ s = s*__expf(mx-v) + 1.f; mx = v; }
        else s += __expf(v-mx);
    }
    cmax[b*n1 + c] = mx;
    csum[b*n1 + c] = s;
}

__global__ void conf_kernel(const float* __restrict__ S,
    const float* __restrict__ rmax, const float* __restrict__ rsum,
    const float* __restrict__ cmax, const float* __restrict__ csum,
    float* __restrict__ conf)
{
    size_t idx = (size_t)blockIdx.x*256 + threadIdx.x;
    int z = (int)(idx / ((size_t)NB*NB));
    size_t rem = idx - (size_t)z*NB*NB;
    int n = (int)(rem / NB), m = (int)(rem % NB);
    float s = S[idx];
    conf[idx] = __expf(2.f*s - rmax[z*NB+n] - cmax[z*NB+m])
                / (rsum[z*NB+n]*csum[z*NB+m]);
}

__global__ void __launch_bounds__(256) rowargmax_kernel(
    const float* __restrict__ conf0, int* i0, float* m0)
{
    int n = blockIdx.x;
    const float* row = conf0 + (size_t)n*NB;
    int tid = threadIdx.x;
    float best = -1e30f; int bidx = 0;
    for (int m=tid;m<NB;m+=256){ float v=row[m]; if (v>best){best=v;bidx=m;} }
    __shared__ float bv[256]; __shared__ int bi[256];
    bv[tid]=best; bi[tid]=bidx; __syncthreads();
    for (int st=128;st;st>>=1){
        if (tid<st){
            if (bv[tid+st]>bv[tid] || (bv[tid+st]==bv[tid] && bi[tid+st]<bi[tid])){
                bv[tid]=bv[tid+st]; bi[tid]=bi[tid+st];
            }
        }
        __syncthreads();
    }
    if (tid==0){ i0[n]=bi[0]; m0[n]=bv[0]; }
}

__global__ void colargmax_kernel(const float* __restrict__ conf0, int* i1, float* m1)
{
    int m = blockIdx.x*256 + threadIdx.x;
    float best = -1e30f; int bidx = 0;
    for (int n=0;n<NB;n++){
        float v = conf0[(size_t)n*NB + m];
        if (v > best){ best=v; bidx=n; }
    }
    i1[m]=bidx; m1[m]=best;
}

__global__ void match0_kernel(const int* i0, const int* i1, const float* m0,
                              float* out, float* ms0buf, int* valid0)
{
    int n = blockIdx.x*256 + threadIdx.x;
    int t = i0[n];
    int mutual = (i1[t] == n);
    float ms0 = mutual ? m0[n] : 0.f;
    int v0 = mutual && (ms0 > 0.2f);
    out[n] = v0 ? (float)t : -1.f;
    out[2*NB + n] = ms0;
    ms0buf[n] = ms0;
    valid0[n] = v0;
}

__global__ void match1_kernel(const int* i0, const int* i1,
                              const float* ms0buf, const int* valid0, float* out)
{
    int m = blockIdx.x*256 + threadIdx.x;
    int t = i1[m];
    int mutual = (i0[t] == m);
    float ms1 = mutual ? ms0buf[t] : 0.f;
    int v1 = mutual && valid0[t];
    out[NB + m] = v1 ? (float)t : -1.f;
    out[3*NB + m] = ms1;
}

/* --------------------------------- host ---------------------------------- */
static void* gsym(const void* s){ void* p=nullptr; cudaGetSymbolAddress(&p, s); return p; }
typedef unsigned short u16;

extern "C" void kernel_launch(void* const* d_in, const int* in_sizes, int n_in,
                              void* d_out, int out_size)
{
    const float* in_dq   = (const float*)d_in[0];
    const float* in_d3   = (const float*)d_in[1];
    const float* in_d2db = (const float*)d_in[2];
    const float* projb   = (const float*)d_in[4];
    const float* mergeb  = (const float*)d_in[6];
    const float* mlp1b   = (const float*)d_in[8];
    const float* mlp2b   = (const float*)d_in[10];
    const float* gatW    = (const float*)d_in[11];
    const float* gata    = (const float*)d_in[12];
    const float* finb    = (const float*)d_in[14];
    float* out = (float*)d_out;

    float* act    = (float*)gsym(g_act);
    float* qkv    = (float*)gsym(g_qkv);
    float* ob     = (float*)gsym(g_ob);
    float* msg    = (float*)gsym(g_msg);
    float* tb     = (float*)gsym(g_tb);
    float* agg    = (float*)gsym(g_agg);
    float* fb     = (float*)gsym(g_fb);
    u16*   fbh    = (u16*)gsym(g_fbh);
    u16*   fbl    = (u16*)gsym(g_fbl);
    float* sc     = (float*)gsym(g_sc);
    float* kvpart = (float*)gsym(g_kvpart);
    float* kvred  = (float*)gsym(g_kvred);
    float* wa     = (float*)gsym(g_wa);
    float* rmax   = (float*)gsym(g_rmax);
    float* rsum   = (float*)gsym(g_rsum);
    float* cmax   = (float*)gsym(g_cmax);
    float* csum   = (float*)gsym(g_csum);
    int*   i0     = (int*)gsym(g_i0);
    int*   i1     = (int*)gsym(g_i1);
    int*   valid0 = (int*)gsym(g_valid0);
    float* m0     = (float*)gsym(g_m0);
    float* m1     = (float*)gsym(g_m1);
    float* ms0buf = (float*)gsym(g_ms0buf);
    u16*   wbh    = (u16*)gsym(g_wbh);
    u16*   wbl    = (u16*)gsym(g_wbl);

    const int N = NB;
    const long long DN  = (long long)DD*N;
    const long long QKN = (long long)3*DD*N;
    const long long TBN = (long long)2*DD*N;
    float* dqp = act;
    float* d3p = act + 2*DN;
    float* dqo = act + 4*DN;

    cvt_all<<<(WTOT/4+255)/256,256>>>((const float*)d_in[3], (const float*)d_in[5],
                                      (const float*)d_in[7], (const float*)d_in[9],
                                      gatW, (const float*)d_in[13], wbh, wbl);

    cudaMemcpyAsync(dqp, in_dq, (size_t)2*DN*sizeof(float), cudaMemcpyDeviceToDevice);
    cudaMemcpyAsync(d3p, in_d3, (size_t)2*DN*sizeof(float), cudaMemcpyDeviceToDevice);
    gat_vec_kernel<<<4,256>>>(gatW, gata, wa);

    int gi = 0, ai = 0;
    for (int step = 0; step < 12; step++) {
        int t = step % 3;
        if (t == 0) {
            gat_agg_kernel<<<dim3(N/8,2),256>>>(d3p, in_d2db, wa + gi*2*DD, agg, N);
            gemm_tc<64,1><<<dim3(N/64,4,2),128>>>(wbh+OFF_GAT+(size_t)gi*DD*DD,
                wbl+OFF_GAT+(size_t)gi*DD*DD, 0, DD,
                agg, DN, agg, DN, DD, nullptr, nullptr,0,
                d3p, DN, DD, N, 1.f, 2);
            gi++;
        } else {
            const u16* pwh = wbh + OFF_PROJ + (size_t)ai*3*DD*DD;
            const u16* pwl = wbl + OFF_PROJ + (size_t)ai*3*DD*DD;
            const float* pb = projb + (size_t)ai*3*DD;
            if (t == 1) {
                gemm_tc<128,0><<<dim3(N/64,6,4),128>>>(pwh, pwl, 0, 768,
                    act, DN, act, DN, DD, pb, nullptr,0, qkv, QKN, DD, N, 1.f, 0);
            } else {
                cudaMemcpyAsync(dqo, dqp, (size_t)2*DN*sizeof(float),
                                cudaMemcpyDeviceToDevice);
                gemm_tc<128,0><<<dim3(N/64,2,4),128>>>(pwh, pwl, 0, DD,
                    act, DN, act, DN, DD, pb, nullptr,0, qkv, QKN, DD, N, 1.f, 0);
                gemm_tc<128,0><<<dim3(N/64,4,4),128>>>(pwh+DD*DD, pwl+DD*DD, 0, 512,
                    d3p, DN, d3p, DN, DD, pb+DD, nullptr,0,
                    qkv + (size_t)DD*N, QKN, DD, N, 1.f, 0);
            }
            attn_kv_kernel<<<dim3(NCHUNK,4,4),256>>>(qkv + (size_t)DD*N, QKN,
                                                     qkv + (size_t)2*DD*N, QKN,
                                                     kvpart, N);
            kv_reduce_kernel<<<(KVSLOT+255)/256,256>>>(kvpart, kvred);
            attn_out_kernel<<<dim3(N/128,4,4),128>>>(qkv, QKN, kvred, ob, DN, N, N);
            gemm_tc<128,0><<<dim3(N/64,2,4),128>>>(wbh+OFF_MERGE+(size_t)ai*DD*DD,
                wbl+OFF_MERGE+(size_t)ai*DD*DD, 0, DD,
                ob, DN, ob, DN, DD, mergeb+(size_t)ai*DD, nullptr,0,
                msg, DN, DD, N, 1.f, 0);
            gemm_tc<128,0><<<dim3(N/64,4,4),128>>>(wbh+OFF_MLP1+(size_t)ai*512*512,
                wbl+OFF_MLP1+(size_t)ai*512*512, 0, 512,
                act, DN, msg, DN, DD, mlp1b+(size_t)ai*512, nullptr,0,
                tb, TBN, 512, N, 1.f, 0);
            instnorm_relu_kernel<<<dim3(512,4),256>>>(tb, 512, N);
            gemm_tc<128,0><<<dim3(N/64,2,4),128>>>(wbh+OFF_MLP2+(size_t)ai*DD*512,
                wbl+OFF_MLP2+(size_t)ai*DD*512, 0, DD,
                tb, TBN, tb, TBN, 512, mlp2b+(size_t)ai*DD, act, DN,
                act, DN, 512, N, 1.f, 0);
            ai++;
        }
    }

    gemm_tc<128,0><<<dim3(N/64,2,4),128>>>(wbh+OFF_FIN, wbl+OFF_FIN, 0, DD,
        act, DN, act, DN, DD, finb, nullptr,0, fb, DN, DD, N, 1.f, 0);
    colnorm_kernel<<<dim3(N/256,4),256>>>(fb, fbh, fbl, N);

    gemm_tc<128,1><<<dim3(N/64,N/128,2),128>>>(fbh, fbl, DN, N,
        fb + 2*DN, DN, fb + 2*DN, DN, DD,
        nullptr, nullptr,0, sc, (long long)N*N, DD, N, 10.f, 0);
    row_stats_kernel<<<dim3(N,2),256>>>(sc, rmax, rsum, N, N);
    col_stats_kernel<<<dim3(N/256,2),256>>>(sc, cmax, csum, N, N);

    float* conf = out + 4*NB;
    conf_kernel<<<(unsigned)((size_t)2*N*N/256),256>>>(sc, rmax, rsum, cmax, csum, conf);
    rowargmax_kernel<<<N,256>>>(conf, i0, m0);
    colargmax_kernel<<<N/256,256>>>(conf, i1, m1);
    match0_kernel<<<N/256,256>>>(i0, i1, m0, out, ms0buf, valid0);
    match1_kernel<<<N/256,256>>>(i0, i1, ms0buf, valid0, out);
}